// round 2
// baseline (speedup 1.0000x reference)
#include <cuda_runtime.h>

// ---------------------------------------------------------------------------
// LanguagePuzzleVAESmall: fused VQ-VAE forward
// B=2048, L=128, V=128, E=32, D=64, NC=10
// Outputs (float32, concatenated): char_logits[B,128,128], puzzles[B,30,30],
// features[B,30,30,64], quantized_st[B,30,30,64], vq_loss[1]
// ---------------------------------------------------------------------------

constexpr int B_ = 2048, L_ = 128, V_ = 128, E_ = 32, D_ = 64, NC_ = 10;

constexpr long long OFF_PUZ   = (long long)B_ * L_ * V_;                 // 33,554,432
constexpr long long OFF_FEAT  = OFF_PUZ  + (long long)B_ * 30 * 30;      // +1,843,200
constexpr long long OFF_QUANT = OFF_FEAT + (long long)B_ * 900 * 64;
constexpr long long OFF_LOSS  = OFF_QUANT + (long long)B_ * 900 * 64;    // 271,327,232

// scratch (device globals: no runtime allocation allowed)
__device__ float g_proj1[V_ * 3 * 64];   // conv1 folded into embedding: [v][k][o]
__device__ float g_P1[NC_ * 3 * 64];     // convT1 folded into codebook: [c][k][o]
__device__ int   g_codes[B_ * 30];
__device__ float g_loss[B_];

// ---------------------------------------------------------------------------
// precompute: proj1[v][k][o] = sum_i enc_w1[o][i][k] * emb[v][i]
// ---------------------------------------------------------------------------
__global__ void pre1_kernel(const float* __restrict__ enc_w1,
                            const float* __restrict__ emb)
{
    int u = blockIdx.x * blockDim.x + threadIdx.x;
    if (u >= V_ * 3 * 64) return;
    int v = u / 192, r = u % 192, k = r / 64, o = r % 64;
    float s = 0.f;
#pragma unroll
    for (int i = 0; i < 32; i++)
        s += enc_w1[(o * 32 + i) * 3 + k] * emb[v * 32 + i];
    g_proj1[u] = s;   // u == (v*3+k)*64+o
}

// precompute: P1[c][k][o] = sum_d dec_w1[d][o][k] * cb[c][d]
__global__ void pre2_kernel(const float* __restrict__ dec_w1,
                            const float* __restrict__ cb)
{
    int u = blockIdx.x * blockDim.x + threadIdx.x;
    if (u >= NC_ * 3 * 64) return;
    int c = u / 192, r = u % 192, k = r / 64, o = r % 64;
    float s = 0.f;
#pragma unroll
    for (int d = 0; d < 64; d++)
        s += dec_w1[(d * 64 + o) * 3 + k] * cb[c * 64 + d];
    g_P1[u] = s;
}

// ---------------------------------------------------------------------------
// Encoder + VQ + broadcast writes. One block per batch element.
// smem floats: h1 4288 | w2t 12288 | h2 2240 | w3t 12288 | enc 1950 | cb 640
//              c2 16 | b1/b2/b3 192 | lp 32 | tok 128 | code 32  = 34,094 (133 KB)
// ---------------------------------------------------------------------------
constexpr int ENC_SMEM_FLOATS = 4288 + 12288 + 2240 + 12288 + 1950 + 640 + 16
                              + 192 + 32 + 128 + 32;
constexpr int ENC_SMEM_BYTES = ENC_SMEM_FLOATS * 4;

__global__ void __launch_bounds__(512, 1)
enc_kernel(const int* __restrict__ tidx,
           const float* __restrict__ b1g, const float* __restrict__ w2g,
           const float* __restrict__ b2g, const float* __restrict__ w3g,
           const float* __restrict__ b3g, const float* __restrict__ cbg,
           float* __restrict__ out)
{
    extern __shared__ float sm[];
    float* s_h1  = sm;                  // 64 x 67, idx = o*67 + (pos+1), zero-padded
    float* s_w2t = s_h1 + 4288;         // [i][k][o]  12288
    float* s_h2  = s_w2t + 12288;       // 64 x 35  (idx o*35 + t)
    float* s_w3t = s_h2 + 2240;         // [i][k][d]  12288
    float* s_enc = s_w3t + 12288;       // 30 x 65 (idx i*65 + d)
    float* s_cb  = s_enc + 1950;        // 10 x 64
    float* s_c2  = s_cb + 640;          // 16
    float* s_b1  = s_c2 + 16;
    float* s_b2  = s_b1 + 64;
    float* s_b3  = s_b2 + 64;
    float* s_lp  = s_b3 + 64;           // 32
    int*   s_tok = (int*)(s_lp + 32);   // 128
    int*   s_code = s_tok + 128;        // 32

    const int tid = threadIdx.x;
    const int b = blockIdx.x;

    // ---- stage A: loads / zero pads ----
    if (tid < 128) s_tok[tid] = tidx[b * 128 + tid];
    for (int u = tid; u < 12288; u += 512) {
        int o = u / 192, i = (u % 192) / 3, k = u % 3;   // enc_w2[o][i][k]
        s_w2t[(i * 3 + k) * 64 + o] = w2g[u];
    }
    for (int u = tid; u < 12288; u += 512) {
        int d = u / 192, i = (u % 192) / 3, k = u % 3;   // enc_w3[d][i][k]
        s_w3t[(i * 3 + k) * 64 + d] = w3g[u];
    }
    for (int u = tid; u < 640; u += 512) s_cb[u] = cbg[u];
    if (tid < 64) { s_b1[tid] = b1g[tid]; s_b2[tid] = b2g[tid]; s_b3[tid] = b3g[tid]; }
    for (int u = tid; u < 4288; u += 512) s_h1[u] = 0.f;
    __syncthreads();

    if (tid < NC_) {
        float s = 0.f;
#pragma unroll
        for (int d = 0; d < 64; d++) { float c = s_cb[tid * 64 + d]; s += c * c; }
        s_c2[tid] = s;
    }

    // ---- conv1 (k3 s2 p1) via folded embedding table + ReLU ----
    {
        int o = tid & 63, g = tid >> 6;      // g in 0..7, 8 t per thread
        float bb = s_b1[o];
#pragma unroll
        for (int j = 0; j < 8; j++) {
            int t = g * 8 + j;
            int p0 = 2 * t - 1;
            float acc = bb;
            if (p0 >= 0) acc += g_proj1[(s_tok[p0] * 3 + 0) * 64 + o];
            acc += g_proj1[(s_tok[p0 + 1] * 3 + 1) * 64 + o];
            acc += g_proj1[(s_tok[p0 + 2] * 3 + 2) * 64 + o];
            s_h1[o * 67 + t + 1] = fmaxf(acc, 0.f);
        }
    }
    __syncthreads();

    // ---- conv2 (64->64, k3 s2 p1) + ReLU ----
    {
        int o = tid & 63, g = tid >> 6;
        int tb = g * 4;
        float bb = s_b2[o];
        float a0 = bb, a1 = bb, a2 = bb, a3 = bb;
#pragma unroll 4
        for (int i = 0; i < 64; i++) {
            const float* hr = s_h1 + i * 67 + 2 * tb;   // h1p idx 2t+k
            float h0 = hr[0], h1v = hr[1], h2v = hr[2], h3 = hr[3], h4 = hr[4];
            float h5 = hr[5], h6 = hr[6], h7 = hr[7], h8 = hr[8];
            const float* wr = s_w2t + i * 192 + o;
            float w0 = wr[0], w1 = wr[64], w2 = wr[128];
            a0 += w0 * h0  + w1 * h1v + w2 * h2v;
            a1 += w0 * h2v + w1 * h3  + w2 * h4;
            a2 += w0 * h4  + w1 * h5  + w2 * h6;
            a3 += w0 * h6  + w1 * h7  + w2 * h8;
        }
        s_h2[o * 35 + tb + 0] = fmaxf(a0, 0.f);
        s_h2[o * 35 + tb + 1] = fmaxf(a1, 0.f);
        s_h2[o * 35 + tb + 2] = fmaxf(a2, 0.f);
        s_h2[o * 35 + tb + 3] = fmaxf(a3, 0.f);
    }
    __syncthreads();

    // ---- conv3 (64->D, k3 s1 p0), no relu ----
    {
        int d = tid & 63, g = tid >> 6;
        int tb = g * 4;
        float bb = s_b3[d];
        float a0 = bb, a1 = bb, a2 = bb, a3 = bb;
#pragma unroll 4
        for (int i = 0; i < 64; i++) {
            const float* hr = s_h2 + i * 35 + tb;
            float h0 = hr[0], h1v = hr[1], h2v = hr[2], h3 = hr[3], h4 = hr[4], h5 = hr[5];
            const float* wr = s_w3t + i * 192 + d;
            float w0 = wr[0], w1 = wr[64], w2 = wr[128];
            a0 += w0 * h0  + w1 * h1v + w2 * h2v;
            a1 += w0 * h1v + w1 * h2v + w2 * h3;
            a2 += w0 * h2v + w1 * h3  + w2 * h4;
            a3 += w0 * h3  + w1 * h4  + w2 * h5;
        }
        if (tb + 0 < 30) s_enc[(tb + 0) * 65 + d] = a0;
        if (tb + 1 < 30) s_enc[(tb + 1) * 65 + d] = a1;
        if (tb + 2 < 30) s_enc[(tb + 2) * 65 + d] = a2;
        if (tb + 3 < 30) s_enc[(tb + 3) * 65 + d] = a3;
    }
    __syncthreads();

    // ---- VQ: argmin over 10 codes (reference d2 formula), loss direct ----
    if (tid < 30) {
        const float* f = s_enc + tid * 65;
        float f2 = 0.f;
#pragma unroll
        for (int d = 0; d < 64; d++) f2 += f[d] * f[d];
        float best = 3.4e38f; int bc = 0;
        for (int c = 0; c < NC_; c++) {
            const float* cr = s_cb + c * 64;
            float dot = 0.f;
#pragma unroll
            for (int d = 0; d < 64; d++) dot += f[d] * cr[d];
            float d2 = f2 - 2.f * dot + s_c2[c];
            if (d2 < best) { best = d2; bc = c; }
        }
        s_code[tid] = bc;
        const float* cr = s_cb + bc * 64;
        float ls = 0.f;
#pragma unroll
        for (int d = 0; d < 64; d++) { float df = f[d] - cr[d]; ls += df * df; }
        s_lp[tid] = ls;
        g_codes[b * 30 + tid] = bc;
    }
    __syncthreads();
    if (tid == 0) {
        float s = 0.f;
        for (int i = 0; i < 30; i++) s += s_lp[i];
        g_loss[b] = s;
    }

    // ---- broadcast writes: features / quantized_st / puzzles (128-bit) ----
    {
        float4* feat4  = (float4*)(out + OFF_FEAT  + (long long)b * 57600);
        float4* quant4 = (float4*)(out + OFF_QUANT + (long long)b * 57600);
        for (int u = tid; u < 14400; u += 512) {
            int i  = u / 480;                // 30 j * 16 d4-groups per i
            int d4 = (u & 15) * 4;
            const float* er = s_enc + i * 65 + d4;
            float4 fv = make_float4(er[0], er[1], er[2], er[3]);
            const float* qr = s_cb + s_code[i] * 64 + d4;
            float4 qv = make_float4(qr[0], qr[1], qr[2], qr[3]);
            feat4[u]  = fv;
            quant4[u] = qv;
        }
        float* puz = out + OFF_PUZ + (long long)b * 900;
        for (int u = tid; u < 900; u += 512)
            puz[u] = (float)s_code[u / 30];
    }
}

// ---------------------------------------------------------------------------
// Decoder + output projection. One block per batch element.
// smem floats: P1 1920 | h1p 2240 | w2t 16384 | h2p 4288 | w3t 8192 |
//              dec 4128 | owt 4096 | biases 288 | code 32 = 41,568 (162 KB)
// ---------------------------------------------------------------------------
constexpr int DEC_SMEM_FLOATS = 1920 + 2240 + 16384 + 4288 + 8192 + 4128 + 4096
                              + 288 + 32;
constexpr int DEC_SMEM_BYTES = DEC_SMEM_FLOATS * 4;

__global__ void __launch_bounds__(512, 1)
dec_kernel(const float* __restrict__ b1g,
           const float* __restrict__ w2g, const float* __restrict__ b2g,
           const float* __restrict__ w3g, const float* __restrict__ b3g,
           const float* __restrict__ owg, const float* __restrict__ obg,
           float* __restrict__ out)
{
    extern __shared__ float sm[];
    float* s_P1  = sm;                    // 1920
    float* s_h1p = s_P1 + 1920;           // 64 x 35 (idx o*35 + s+1), zero padded
    float* s_w2t = s_h1p + 2240;          // [d][k][o] 16384
    float* s_h2p = s_w2t + 16384;         // 64 x 67 (idx o*67 + t+1), zero padded
    float* s_w3t = s_h2p + 4288;          // [d][k][e] 8192
    float* s_dec = s_w3t + 8192;          // 32 x 129 (idx e*129 + l)
    float* s_owt = s_dec + 4128;          // [e][v] 4096
    float* s_b1  = s_owt + 4096;          // 64
    float* s_b2  = s_b1 + 64;             // 64
    float* s_b3  = s_b2 + 64;             // 32
    float* s_ob  = s_b3 + 32;             // 128
    int*   s_code = (int*)(s_ob + 128);   // 32

    const int tid = threadIdx.x;
    const int b = blockIdx.x;

    for (int u = tid; u < 1920; u += 512) s_P1[u] = g_P1[u];
    if (tid < 30) s_code[tid] = g_codes[b * 30 + tid];
    for (int u = tid; u < 16384; u += 512) {
        int d = u >> 8, o = (u >> 2) & 63, k = u & 3;    // dec_w2[d][o][k]
        s_w2t[(d * 4 + k) * 64 + o] = w2g[u];
    }
    for (int u = tid; u < 8192; u += 512) {
        int d = u >> 7, e = (u >> 2) & 31, k = u & 3;    // dec_w3[d][e][k]
        s_w3t[(d * 4 + k) * 32 + e] = w3g[u];
    }
    for (int u = tid; u < 4096; u += 512) {
        int v = u >> 5, e = u & 31;                       // out_w[v][e]
        s_owt[e * 128 + v] = owg[u];
    }
    if (tid < 64) { s_b1[tid] = b1g[tid]; s_b2[tid] = b2g[tid]; }
    if (tid < 32) s_b3[tid] = b3g[tid];
    if (tid < 128) s_ob[tid] = obg[tid];
    for (int u = tid; u < 2240; u += 512) s_h1p[u] = 0.f;
    for (int u = tid; u < 4288; u += 512) s_h2p[u] = 0.f;
    __syncthreads();

    // ---- convT1 (s1 p0 k3) via folded codebook table + ReLU ----
    {
        int o = tid & 63, g = tid >> 6;
        float bb = s_b1[o];
#pragma unroll
        for (int j = 0; j < 4; j++) {
            int t = g * 4 + j;                     // 0..31
            float acc = bb;
#pragma unroll
            for (int k = 0; k < 3; k++) {
                int s = t - k;
                if (s >= 0 && s < 30)
                    acc += s_P1[(s_code[s] * 3 + k) * 64 + o];
            }
            s_h1p[o * 35 + t + 1] = fmaxf(acc, 0.f);
        }
    }
    __syncthreads();

    // ---- convT2 (s2 p1 k4) + ReLU : out [64][64] ----
    {
        int o = tid & 63, g = tid >> 6;            // 8 t per thread
        int tb = g * 8;
        int sb = tb / 2 - 1;
        float bb = s_b2[o];
        float acc[8];
#pragma unroll
        for (int j = 0; j < 8; j++) acc[j] = bb;
#pragma unroll 2
        for (int d = 0; d < 64; d++) {
            const float* wr = s_w2t + d * 256 + o;
            float w0 = wr[0], w1 = wr[64], w2 = wr[128], w3 = wr[192];
            const float* hr = s_h1p + d * 35 + sb + 1;
            float l0 = hr[0], l1 = hr[1], l2 = hr[2], l3 = hr[3], l4 = hr[4], l5 = hr[5];
            acc[0] += w1 * l1 + w3 * l0;
            acc[2] += w1 * l2 + w3 * l1;
            acc[4] += w1 * l3 + w3 * l2;
            acc[6] += w1 * l4 + w3 * l3;
            acc[1] += w0 * l2 + w2 * l1;
            acc[3] += w0 * l3 + w2 * l2;
            acc[5] += w0 * l4 + w2 * l3;
            acc[7] += w0 * l5 + w2 * l4;
        }
#pragma unroll
        for (int j = 0; j < 8; j++)
            s_h2p[o * 67 + tb + j + 1] = fmaxf(acc[j], 0.f);
    }
    __syncthreads();

    // ---- convT3 (s2 p1 k4) : out [32][128], +b3, no relu ----
    {
        int e = tid & 31, g = tid >> 5;            // 8 l per thread
        int lb = g * 8;
        int sb = lb / 2 - 1;
        float bb = s_b3[e];
        float acc[8];
#pragma unroll
        for (int j = 0; j < 8; j++) acc[j] = bb;
#pragma unroll 2
        for (int d = 0; d < 64; d++) {
            const float* wr = s_w3t + d * 128 + e;
            float w0 = wr[0], w1 = wr[32], w2 = wr[64], w3 = wr[96];
            const float* hr = s_h2p + d * 67 + sb + 1;
            float l0 = hr[0], l1 = hr[1], l2 = hr[2], l3 = hr[3], l4 = hr[4], l5 = hr[5];
            acc[0] += w1 * l1 + w3 * l0;
            acc[2] += w1 * l2 + w3 * l1;
            acc[4] += w1 * l3 + w3 * l2;
            acc[6] += w1 * l4 + w3 * l3;
            acc[1] += w0 * l2 + w2 * l1;
            acc[3] += w0 * l3 + w2 * l2;
            acc[5] += w0 * l4 + w2 * l3;
            acc[7] += w0 * l5 + w2 * l4;
        }
#pragma unroll
        for (int j = 0; j < 8; j++)
            s_dec[e * 129 + lb + j] = acc[j];
    }
    __syncthreads();

    // ---- projection: logits[l][v] = sum_e dec[e][l]*out_w[v][e] + out_b[v] ----
    {
        int v0 = tid & 63, g = tid >> 6;
        int lb = g * 16;
        float a0[16], a1[16];
#pragma unroll
        for (int j = 0; j < 16; j++) { a0[j] = 0.f; a1[j] = 0.f; }
#pragma unroll 4
        for (int e = 0; e < 32; e++) {
            float wv0 = s_owt[e * 128 + v0];
            float wv1 = s_owt[e * 128 + v0 + 64];
            const float* dr = s_dec + e * 129 + lb;
#pragma unroll
            for (int j = 0; j < 16; j++) {
                float dl = dr[j];
                a0[j] += wv0 * dl;
                a1[j] += wv1 * dl;
            }
        }
        float* lg = out + (long long)b * (128 * 128);
        float ob0 = s_ob[v0], ob1 = s_ob[v0 + 64];
#pragma unroll
        for (int j = 0; j < 16; j++) {
            lg[(lb + j) * 128 + v0]      = a0[j] + ob0;
            lg[(lb + j) * 128 + v0 + 64] = a1[j] + ob1;
        }
    }
}

// ---------------------------------------------------------------------------
// vq_loss reduce
// ---------------------------------------------------------------------------
__global__ void loss_kernel(float* __restrict__ out)
{
    __shared__ float red[256];
    int tid = threadIdx.x;
    float s = 0.f;
    for (int u = tid; u < B_; u += 256) s += g_loss[u];
    red[tid] = s;
    __syncthreads();
    for (int st = 128; st > 0; st >>= 1) {
        if (tid < st) red[tid] += red[tid + st];
        __syncthreads();
    }
    if (tid == 0)
        out[OFF_LOSS] = 1.25f * red[0] / (float)(B_ * 30 * 64);
}

// ---------------------------------------------------------------------------
extern "C" void kernel_launch(void* const* d_in, const int* in_sizes, int n_in,
                              void* d_out, int out_size)
{
    (void)in_sizes; (void)n_in; (void)out_size;
    const int*   tidx = (const int*)d_in[0];
    const float* emb  = (const float*)d_in[1];
    const float* ew1  = (const float*)d_in[2];
    const float* eb1  = (const float*)d_in[3];
    const float* ew2  = (const float*)d_in[4];
    const float* eb2  = (const float*)d_in[5];
    const float* ew3  = (const float*)d_in[6];
    const float* eb3  = (const float*)d_in[7];
    const float* cb   = (const float*)d_in[8];
    const float* dw1  = (const float*)d_in[9];
    const float* db1  = (const float*)d_in[10];
    const float* dw2  = (const float*)d_in[11];
    const float* db2  = (const float*)d_in[12];
    const float* dw3  = (const float*)d_in[13];
    const float* db3  = (const float*)d_in[14];
    const float* ow   = (const float*)d_in[15];
    const float* ob   = (const float*)d_in[16];
    float* out = (float*)d_out;

    cudaFuncSetAttribute(enc_kernel, cudaFuncAttributeMaxDynamicSharedMemorySize,
                         ENC_SMEM_BYTES);
    cudaFuncSetAttribute(dec_kernel, cudaFuncAttributeMaxDynamicSharedMemorySize,
                         DEC_SMEM_BYTES);

    pre1_kernel<<<48, 512>>>(ew1, emb);
    pre2_kernel<<<4, 512>>>(dw1, cb);
    enc_kernel<<<B_, 512, ENC_SMEM_BYTES>>>(tidx, eb1, ew2, eb2, ew3, eb3, cb, out);
    dec_kernel<<<B_, 512, DEC_SMEM_BYTES>>>(db1, dw2, db2, dw3, db3, ow, ob, out);
    loss_kernel<<<1, 256>>>(out);
}

// round 3
// speedup vs baseline: 1.1050x; 1.1050x over previous
#include <cuda_runtime.h>

// ---------------------------------------------------------------------------
// LanguagePuzzleVAESmall: fused VQ-VAE forward
// B=2048, L=128, V=128, E=32, D=64, NC=10
// Outputs (float32, concatenated): char_logits[B,128,128], puzzles[B,30,30],
// features[B,30,30,64], quantized_st[B,30,30,64], vq_loss[1]
// ---------------------------------------------------------------------------

constexpr int B_ = 2048, L_ = 128, V_ = 128, E_ = 32, D_ = 64, NC_ = 10;

constexpr long long OFF_PUZ   = (long long)B_ * L_ * V_;                 // 33,554,432
constexpr long long OFF_FEAT  = OFF_PUZ  + (long long)B_ * 30 * 30;      // +1,843,200
constexpr long long OFF_QUANT = OFF_FEAT + (long long)B_ * 900 * 64;
constexpr long long OFF_LOSS  = OFF_QUANT + (long long)B_ * 900 * 64;    // 271,327,232

// scratch (device globals: no runtime allocation allowed)
__device__ float g_proj1[V_ * 3 * 64];   // conv1 folded into embedding: [v][k][o]
__device__ float g_P1[NC_ * 3 * 64];     // convT1 folded into codebook: [c][k][o]
__device__ int   g_codes[B_ * 32];
__device__ float g_loss[B_];
__device__ float g_enc[(long long)B_ * 1920];   // [b][i=30][d=64] contiguous

// ---------------------------------------------------------------------------
// precompute: proj1[v][k][o] = sum_i enc_w1[o][i][k] * emb[v][i]
// ---------------------------------------------------------------------------
__global__ void pre1_kernel(const float* __restrict__ enc_w1,
                            const float* __restrict__ emb)
{
    int u = blockIdx.x * blockDim.x + threadIdx.x;
    if (u >= V_ * 3 * 64) return;
    int v = u / 192, r = u % 192, k = r / 64, o = r % 64;
    float s = 0.f;
#pragma unroll
    for (int i = 0; i < 32; i++)
        s += enc_w1[(o * 32 + i) * 3 + k] * emb[v * 32 + i];
    g_proj1[u] = s;   // u == (v*3+k)*64+o
}

// precompute: P1[c][k][o] = sum_d dec_w1[d][o][k] * cb[c][d]
__global__ void pre2_kernel(const float* __restrict__ dec_w1,
                            const float* __restrict__ cb)
{
    int u = blockIdx.x * blockDim.x + threadIdx.x;
    if (u >= NC_ * 3 * 64) return;
    int c = u / 192, r = u % 192, k = r / 64, o = r % 64;
    float s = 0.f;
#pragma unroll
    for (int d = 0; d < 64; d++)
        s += dec_w1[(d * 64 + o) * 3 + k] * cb[c * 64 + d];
    g_P1[u] = s;
}

// ---------------------------------------------------------------------------
// Encoder + VQ. One block per batch element. Writes enc features + codes +
// per-batch loss to scratch; the big broadcast fan-out happens in bcast_kernel.
// ---------------------------------------------------------------------------
constexpr int ENC_SMEM_FLOATS = 4288 + 16384 + 2240 + 16384 + 1952 + 640 + 16
                              + 192 + 32 + 128 + 32;
constexpr int ENC_SMEM_BYTES = ENC_SMEM_FLOATS * 4;

__global__ void __launch_bounds__(512, 1)
enc_kernel(const int* __restrict__ tidx,
           const float* __restrict__ b1g, const float* __restrict__ w2g,
           const float* __restrict__ b2g, const float* __restrict__ w3g,
           const float* __restrict__ b3g, const float* __restrict__ cbg)
{
    extern __shared__ float sm[];
    float* s_h1  = sm;                  // 64 x 67, idx = o*67 + (pos+1), zero-padded
    float* s_w2t = s_h1 + 4288;         // [i][o][k4pad]  16384
    float* s_h2  = s_w2t + 16384;       // 64 x 35  (idx o*35 + t)
    float* s_w3t = s_h2 + 2240;         // [i][d][k4pad]  16384
    float* s_enc = s_w3t + 16384;       // 30 x 65 (idx i*65 + d)
    float* s_cb  = s_enc + 1952;        // 10 x 64
    float* s_c2  = s_cb + 640;          // 16
    float* s_b1  = s_c2 + 16;
    float* s_b2  = s_b1 + 64;
    float* s_b3  = s_b2 + 64;
    float* s_lp  = s_b3 + 64;           // 32
    int*   s_tok = (int*)(s_lp + 32);   // 128
    int*   s_code = s_tok + 128;        // 32

    const int tid = threadIdx.x;
    const int b = blockIdx.x;

    // ---- stage A: loads / transposes / zero pads ----
    if (tid < 128) s_tok[tid] = tidx[b * 128 + tid];
    for (int u = tid; u < 12288; u += 512) {
        int o = u / 192, i = (u % 192) / 3, k = u % 3;   // enc_w2[o][i][k]
        s_w2t[(i * 64 + o) * 4 + k] = w2g[u];
    }
    for (int u = tid; u < 12288; u += 512) {
        int d = u / 192, i = (u % 192) / 3, k = u % 3;   // enc_w3[d][i][k]
        s_w3t[(i * 64 + d) * 4 + k] = w3g[u];
    }
    for (int u = tid; u < 640; u += 512) s_cb[u] = cbg[u];
    if (tid < 64) { s_b1[tid] = b1g[tid]; s_b2[tid] = b2g[tid]; s_b3[tid] = b3g[tid]; }
    for (int u = tid; u < 4288; u += 512) s_h1[u] = 0.f;
    __syncthreads();

    if (tid < NC_) {
        float s = 0.f;
#pragma unroll
        for (int d = 0; d < 64; d++) { float c = s_cb[tid * 64 + d]; s += c * c; }
        s_c2[tid] = s;
    }

    // ---- conv1 (k3 s2 p1) via folded embedding table + ReLU ----
    {
        int o = tid & 63, g = tid >> 6;      // g in 0..7, 8 t per thread
        float bb = s_b1[o];
#pragma unroll
        for (int j = 0; j < 8; j++) {
            int t = g * 8 + j;
            int p0 = 2 * t - 1;
            float acc = bb;
            if (p0 >= 0) acc += g_proj1[(s_tok[p0] * 3 + 0) * 64 + o];
            acc += g_proj1[(s_tok[p0 + 1] * 3 + 1) * 64 + o];
            acc += g_proj1[(s_tok[p0 + 2] * 3 + 2) * 64 + o];
            s_h1[o * 67 + t + 1] = fmaxf(acc, 0.f);
        }
    }
    __syncthreads();

    // ---- conv2 (64->64, k3 s2 p1) + ReLU ----
    {
        int o = tid & 63, g = tid >> 6;
        int tb = g * 4;
        float bb = s_b2[o];
        float a0 = bb, a1 = bb, a2 = bb, a3 = bb;
#pragma unroll 4
        for (int i = 0; i < 64; i++) {
            const float* hr = s_h1 + i * 67 + 2 * tb;   // h1p idx 2t+k
            float h0 = hr[0], h1v = hr[1], h2v = hr[2], h3 = hr[3], h4 = hr[4];
            float h5 = hr[5], h6 = hr[6], h7 = hr[7], h8 = hr[8];
            float4 wv = *(const float4*)(s_w2t + ((i << 6) + o) * 4);
            float w0 = wv.x, w1 = wv.y, w2 = wv.z;
            a0 += w0 * h0  + w1 * h1v + w2 * h2v;
            a1 += w0 * h2v + w1 * h3  + w2 * h4;
            a2 += w0 * h4  + w1 * h5  + w2 * h6;
            a3 += w0 * h6  + w1 * h7  + w2 * h8;
        }
        s_h2[o * 35 + tb + 0] = fmaxf(a0, 0.f);
        s_h2[o * 35 + tb + 1] = fmaxf(a1, 0.f);
        s_h2[o * 35 + tb + 2] = fmaxf(a2, 0.f);
        s_h2[o * 35 + tb + 3] = fmaxf(a3, 0.f);
    }
    __syncthreads();

    // ---- conv3 (64->D, k3 s1 p0), no relu ----
    {
        int d = tid & 63, g = tid >> 6;
        int tb = g * 4;
        float bb = s_b3[d];
        float a0 = bb, a1 = bb, a2 = bb, a3 = bb;
#pragma unroll 4
        for (int i = 0; i < 64; i++) {
            const float* hr = s_h2 + i * 35 + tb;
            float h0 = hr[0], h1v = hr[1], h2v = hr[2], h3 = hr[3], h4 = hr[4], h5 = hr[5];
            float4 wv = *(const float4*)(s_w3t + ((i << 6) + d) * 4);
            float w0 = wv.x, w1 = wv.y, w2 = wv.z;
            a0 += w0 * h0  + w1 * h1v + w2 * h2v;
            a1 += w0 * h1v + w1 * h2v + w2 * h3;
            a2 += w0 * h2v + w1 * h3  + w2 * h4;
            a3 += w0 * h3  + w1 * h4  + w2 * h5;
        }
        if (tb + 0 < 30) s_enc[(tb + 0) * 65 + d] = a0;
        if (tb + 1 < 30) s_enc[(tb + 1) * 65 + d] = a1;
        if (tb + 2 < 30) s_enc[(tb + 2) * 65 + d] = a2;
        if (tb + 3 < 30) s_enc[(tb + 3) * 65 + d] = a3;
    }
    __syncthreads();

    // ---- VQ: argmin over 10 codes (reference d2 formula), loss direct ----
    if (tid < 30) {
        const float* f = s_enc + tid * 65;
        float f2 = 0.f;
#pragma unroll
        for (int d = 0; d < 64; d++) f2 += f[d] * f[d];
        float best = 3.4e38f; int bc = 0;
        for (int c = 0; c < NC_; c++) {
            const float* cr = s_cb + c * 64;
            float dot = 0.f;
#pragma unroll
            for (int d = 0; d < 64; d++) dot += f[d] * cr[d];
            float d2 = f2 - 2.f * dot + s_c2[c];
            if (d2 < best) { best = d2; bc = c; }
        }
        s_code[tid] = bc;
        const float* cr = s_cb + bc * 64;
        float ls = 0.f;
#pragma unroll
        for (int d = 0; d < 64; d++) { float df = f[d] - cr[d]; ls += df * df; }
        s_lp[tid] = ls;
        g_codes[b * 32 + tid] = bc;
    }
    __syncthreads();
    if (tid == 0) {
        float s = 0.f;
        for (int i = 0; i < 30; i++) s += s_lp[i];
        g_loss[b] = s;
    }

    // ---- write enc features to contiguous scratch [30][64] ----
    {
        float* ge = g_enc + (long long)b * 1920;
        for (int u = tid; u < 1920; u += 512)
            ge[u] = s_enc[(u >> 6) * 65 + (u & 63)];
    }
}

// ---------------------------------------------------------------------------
// Broadcast fan-out: features / quantized_st / puzzles. One block per batch.
// High occupancy (tiny smem), pure STG.128 streaming.
// ---------------------------------------------------------------------------
__global__ void __launch_bounds__(256)
bcast_kernel(const float* __restrict__ cbg, float* __restrict__ out)
{
    __shared__ float4 s_enc4[480];   // [i=30][d4=16]
    __shared__ float4 s_cb4[160];    // [c=10][d4=16]
    __shared__ int    s_code[32];

    const int tid = threadIdx.x;
    const int b = blockIdx.x;

    {
        const float4* ge4 = (const float4*)(g_enc + (long long)b * 1920);
        for (int u = tid; u < 480; u += 256) s_enc4[u] = ge4[u];
        const float4* cb4 = (const float4*)cbg;
        if (tid < 160) s_cb4[tid] = cb4[tid];
        if (tid < 30) s_code[tid] = g_codes[b * 32 + tid];
    }
    __syncthreads();

    const int d4 = tid & 15;
    const int jr = tid >> 4;          // 0..15
    float4* feat4  = (float4*)(out + OFF_FEAT  + (long long)b * 57600);
    float4* quant4 = (float4*)(out + OFF_QUANT + (long long)b * 57600);

#pragma unroll 2
    for (int i = 0; i < 30; i++) {
        float4 fv = s_enc4[i * 16 + d4];
        float4 qv = s_cb4[s_code[i] * 16 + d4];
        int base = i * 480;
        feat4 [base + jr * 16 + d4] = fv;
        quant4[base + jr * 16 + d4] = qv;
        if (jr + 16 < 30) {
            feat4 [base + (jr + 16) * 16 + d4] = fv;
            quant4[base + (jr + 16) * 16 + d4] = qv;
        }
    }

    float* puz = out + OFF_PUZ + (long long)b * 900;
    for (int u = tid; u < 900; u += 256)
        puz[u] = (float)s_code[u / 30];
}

// ---------------------------------------------------------------------------
// Decoder + output projection. One block per batch element.
// ---------------------------------------------------------------------------
constexpr int DEC_SMEM_FLOATS = 1920 + 2240 + 16384 + 4288 + 8192 + 4224 + 4096
                              + 288 + 32;
constexpr int DEC_SMEM_BYTES = DEC_SMEM_FLOATS * 4;

__global__ void __launch_bounds__(512, 1)
dec_kernel(const float* __restrict__ b1g,
           const float* __restrict__ w2g, const float* __restrict__ b2g,
           const float* __restrict__ w3g, const float* __restrict__ b3g,
           const float* __restrict__ owg, const float* __restrict__ obg,
           float* __restrict__ out)
{
    extern __shared__ float sm[];
    float* s_P1  = sm;                    // 1920
    float* s_h1p = s_P1 + 1920;           // 64 x 35 (idx o*35 + s+1), zero padded
    float* s_w2t = s_h1p + 2240;          // [d][o][k4] 16384 (native layout)
    float* s_h2p = s_w2t + 16384;         // 64 x 67 (idx o*67 + t+1), zero padded
    float* s_w3t = s_h2p + 4288;          // [d][e][k4] 8192 (native layout)
    float* s_dec = s_w3t + 8192;          // 32 x 132 (idx e*132 + l), float4-aligned
    float* s_owt = s_dec + 4224;          // [e][v] 4096
    float* s_b1  = s_owt + 4096;          // 64
    float* s_b2  = s_b1 + 64;             // 64
    float* s_b3  = s_b2 + 64;             // 32
    float* s_ob  = s_b3 + 32;             // 128
    int*   s_code = (int*)(s_ob + 128);   // 32

    const int tid = threadIdx.x;
    const int b = blockIdx.x;

    for (int u = tid; u < 1920; u += 512) s_P1[u] = g_P1[u];
    if (tid < 30) s_code[tid] = g_codes[b * 32 + tid];
    // dec_w2 [d][o][k4] and dec_w3 [d][e][k4] are already k-contiguous: raw copy
    {
        float4* dst = (float4*)s_w2t; const float4* src = (const float4*)w2g;
        for (int u = tid; u < 4096; u += 512) dst[u] = src[u];
    }
    {
        float4* dst = (float4*)s_w3t; const float4* src = (const float4*)w3g;
        for (int u = tid; u < 2048; u += 512) dst[u] = src[u];
    }
    for (int u = tid; u < 4096; u += 512) {
        int v = u >> 5, e = u & 31;                       // out_w[v][e]
        s_owt[e * 128 + v] = owg[u];
    }
    if (tid < 64) { s_b1[tid] = b1g[tid]; s_b2[tid] = b2g[tid]; }
    if (tid < 32) s_b3[tid] = b3g[tid];
    if (tid < 128) s_ob[tid] = obg[tid];
    for (int u = tid; u < 2240; u += 512) s_h1p[u] = 0.f;
    for (int u = tid; u < 4288; u += 512) s_h2p[u] = 0.f;
    __syncthreads();

    // ---- convT1 (s1 p0 k3) via folded codebook table + ReLU ----
    {
        int o = tid & 63, g = tid >> 6;
        float bb = s_b1[o];
#pragma unroll
        for (int j = 0; j < 4; j++) {
            int t = g * 4 + j;                     // 0..31
            float acc = bb;
#pragma unroll
            for (int k = 0; k < 3; k++) {
                int s = t - k;
                if (s >= 0 && s < 30)
                    acc += s_P1[(s_code[s] * 3 + k) * 64 + o];
            }
            s_h1p[o * 35 + t + 1] = fmaxf(acc, 0.f);
        }
    }
    __syncthreads();

    // ---- convT2 (s2 p1 k4) + ReLU : out [64][64] ----
    {
        int o = tid & 63, g = tid >> 6;            // 8 t per thread
        int tb = g * 8;
        int sb = tb / 2 - 1;
        float bb = s_b2[o];
        float acc[8];
#pragma unroll
        for (int j = 0; j < 8; j++) acc[j] = bb;
#pragma unroll 2
        for (int d = 0; d < 64; d++) {
            float4 wv = *(const float4*)(s_w2t + ((d << 6) + o) * 4);
            float w0 = wv.x, w1 = wv.y, w2 = wv.z, w3 = wv.w;
            const float* hr = s_h1p + d * 35 + sb + 1;
            float l0 = hr[0], l1 = hr[1], l2 = hr[2], l3 = hr[3], l4 = hr[4], l5 = hr[5];
            acc[0] += w1 * l1 + w3 * l0;
            acc[2] += w1 * l2 + w3 * l1;
            acc[4] += w1 * l3 + w3 * l2;
            acc[6] += w1 * l4 + w3 * l3;
            acc[1] += w0 * l2 + w2 * l1;
            acc[3] += w0 * l3 + w2 * l2;
            acc[5] += w0 * l4 + w2 * l3;
            acc[7] += w0 * l5 + w2 * l4;
        }
#pragma unroll
        for (int j = 0; j < 8; j++)
            s_h2p[o * 67 + tb + j + 1] = fmaxf(acc[j], 0.f);
    }
    __syncthreads();

    // ---- convT3 (s2 p1 k4) : out [32][128], +b3, no relu ----
    {
        int e = tid & 31, g = tid >> 5;            // 8 l per thread
        int lb = g * 8;
        int sb = lb / 2 - 1;
        float bb = s_b3[e];
        float acc[8];
#pragma unroll
        for (int j = 0; j < 8; j++) acc[j] = bb;
#pragma unroll 2
        for (int d = 0; d < 64; d++) {
            float4 wv = *(const float4*)(s_w3t + ((d << 5) + e) * 4);
            float w0 = wv.x, w1 = wv.y, w2 = wv.z, w3 = wv.w;
            const float* hr = s_h2p + d * 67 + sb + 1;
            float l0 = hr[0], l1 = hr[1], l2 = hr[2], l3 = hr[3], l4 = hr[4], l5 = hr[5];
            acc[0] += w1 * l1 + w3 * l0;
            acc[2] += w1 * l2 + w3 * l1;
            acc[4] += w1 * l3 + w3 * l2;
            acc[6] += w1 * l4 + w3 * l3;
            acc[1] += w0 * l2 + w2 * l1;
            acc[3] += w0 * l3 + w2 * l2;
            acc[5] += w0 * l4 + w2 * l3;
            acc[7] += w0 * l5 + w2 * l4;
        }
#pragma unroll
        for (int j = 0; j < 8; j++)
            s_dec[e * 132 + lb + j] = acc[j];
    }
    __syncthreads();

    // ---- projection: logits[l][v] = sum_e dec[e][l]*out_w[v][e] + out_b[v] ----
    {
        int v0 = tid & 63, g = tid >> 6;
        int lb = g * 16;
        float a0[16], a1[16];
#pragma unroll
        for (int j = 0; j < 16; j++) { a0[j] = 0.f; a1[j] = 0.f; }
#pragma unroll 4
        for (int e = 0; e < 32; e++) {
            float wv0 = s_owt[e * 128 + v0];
            float wv1 = s_owt[e * 128 + v0 + 64];
            const float4* dr4 = (const float4*)(s_dec + e * 132 + lb);
            float dl[16];
            *(float4*)(dl + 0)  = dr4[0];
            *(float4*)(dl + 4)  = dr4[1];
            *(float4*)(dl + 8)  = dr4[2];
            *(float4*)(dl + 12) = dr4[3];
#pragma unroll
            for (int j = 0; j < 16; j++) {
                a0[j] += wv0 * dl[j];
                a1[j] += wv1 * dl[j];
            }
        }
        float* lg = out + (long long)b * (128 * 128);
        float ob0 = s_ob[v0], ob1 = s_ob[v0 + 64];
#pragma unroll
        for (int j = 0; j < 16; j++) {
            lg[(lb + j) * 128 + v0]      = a0[j] + ob0;
            lg[(lb + j) * 128 + v0 + 64] = a1[j] + ob1;
        }
    }
}

// ---------------------------------------------------------------------------
// vq_loss reduce
// ---------------------------------------------------------------------------
__global__ void loss_kernel(float* __restrict__ out)
{
    __shared__ float red[256];
    int tid = threadIdx.x;
    float s = 0.f;
    for (int u = tid; u < B_; u += 256) s += g_loss[u];
    red[tid] = s;
    __syncthreads();
    for (int st = 128; st > 0; st >>= 1) {
        if (tid < st) red[tid] += red[tid + st];
        __syncthreads();
    }
    if (tid == 0)
        out[OFF_LOSS] = 1.25f * red[0] / (float)(B_ * 30 * 64);
}

// ---------------------------------------------------------------------------
extern "C" void kernel_launch(void* const* d_in, const int* in_sizes, int n_in,
                              void* d_out, int out_size)
{
    (void)in_sizes; (void)n_in; (void)out_size;
    const int*   tidx = (const int*)d_in[0];
    const float* emb  = (const float*)d_in[1];
    const float* ew1  = (const float*)d_in[2];
    const float* eb1  = (const float*)d_in[3];
    const float* ew2  = (const float*)d_in[4];
    const float* eb2  = (const float*)d_in[5];
    const float* ew3  = (const float*)d_in[6];
    const float* eb3  = (const float*)d_in[7];
    const float* cb   = (const float*)d_in[8];
    const float* dw1  = (const float*)d_in[9];
    const float* db1  = (const float*)d_in[10];
    const float* dw2  = (const float*)d_in[11];
    const float* db2  = (const float*)d_in[12];
    const float* dw3  = (const float*)d_in[13];
    const float* db3  = (const float*)d_in[14];
    const float* ow   = (const float*)d_in[15];
    const float* ob   = (const float*)d_in[16];
    float* out = (float*)d_out;

    cudaFuncSetAttribute(enc_kernel, cudaFuncAttributeMaxDynamicSharedMemorySize,
                         ENC_SMEM_BYTES);
    cudaFuncSetAttribute(dec_kernel, cudaFuncAttributeMaxDynamicSharedMemorySize,
                         DEC_SMEM_BYTES);

    pre1_kernel<<<48, 512>>>(ew1, emb);
    pre2_kernel<<<4, 512>>>(dw1, cb);
    enc_kernel<<<B_, 512, ENC_SMEM_BYTES>>>(tidx, eb1, ew2, eb2, ew3, eb3, cb);
    bcast_kernel<<<B_, 256>>>(cb, out);
    dec_kernel<<<B_, 512, DEC_SMEM_BYTES>>>(db1, dw2, db2, dw3, db3, ow, ob, out);
    loss_kernel<<<1, 256>>>(out);
}

// round 5
// speedup vs baseline: 1.1938x; 1.0804x over previous
#include <cuda_runtime.h>

// ---------------------------------------------------------------------------
// LanguagePuzzleVAESmall: fused VQ-VAE forward
// B=2048, L=128, V=128, E=32, D=64, NC=10
// ---------------------------------------------------------------------------

constexpr int B_ = 2048, L_ = 128, V_ = 128, E_ = 32, D_ = 64, NC_ = 10;

constexpr long long OFF_PUZ   = (long long)B_ * L_ * V_;
constexpr long long OFF_FEAT  = OFF_PUZ  + (long long)B_ * 30 * 30;
constexpr long long OFF_QUANT = OFF_FEAT + (long long)B_ * 900 * 64;
constexpr long long OFF_LOSS  = OFF_QUANT + (long long)B_ * 900 * 64;

// scratch (device globals: no runtime allocation allowed)
__device__ float g_proj1[V_ * 3 * 64];   // conv1 folded into embedding: [v][k][o]
__device__ float g_P1[NC_ * 3 * 64];     // convT1 folded into codebook: [c][k][o]
__device__ float g_w2p[64 * 64 * 4];     // enc_w2 packed [i][o][k4]
__device__ float g_w3p[64 * 64 * 4];     // enc_w3 packed [i][d][k4]
__device__ float g_owt[32 * 128];        // out_w packed [e][v]
__device__ int   g_codes[B_ * 32];
__device__ float g_loss[B_];
__device__ float g_enc[(long long)B_ * 1920];   // [b][i=30][d=64]

// ---------------------------------------------------------------------------
__global__ void pre1_kernel(const float* __restrict__ enc_w1,
                            const float* __restrict__ emb)
{
    int u = blockIdx.x * blockDim.x + threadIdx.x;
    if (u >= V_ * 3 * 64) return;
    int v = u / 192, r = u % 192, k = r / 64, o = r % 64;
    float s = 0.f;
#pragma unroll
    for (int i = 0; i < 32; i++)
        s += enc_w1[(o * 32 + i) * 3 + k] * emb[v * 32 + i];
    g_proj1[u] = s;
}

__global__ void pre2_kernel(const float* __restrict__ dec_w1,
                            const float* __restrict__ cb)
{
    int u = blockIdx.x * blockDim.x + threadIdx.x;
    if (u >= NC_ * 3 * 64) return;
    int c = u / 192, r = u % 192, k = r / 64, o = r % 64;
    float s = 0.f;
#pragma unroll
    for (int d = 0; d < 64; d++)
        s += dec_w1[(d * 64 + o) * 3 + k] * cb[c * 64 + d];
    g_P1[u] = s;
}

// pack enc_w2/enc_w3 -> [i][ch][k4], out_w -> [e][v]
__global__ void pre3_kernel(const float* __restrict__ w2g,
                            const float* __restrict__ w3g,
                            const float* __restrict__ owg)
{
    int u = blockIdx.x * blockDim.x + threadIdx.x;
    if (u < 16384) {
        int i = u >> 8, o = (u >> 2) & 63, k = u & 3;
        g_w2p[u] = (k < 3) ? w2g[o * 192 + i * 3 + k] : 0.f;
    } else if (u < 32768) {
        int w = u - 16384;
        int i = w >> 8, d = (w >> 2) & 63, k = w & 3;
        g_w3p[w] = (k < 3) ? w3g[d * 192 + i * 3 + k] : 0.f;
    } else if (u < 32768 + 4096) {
        int w = u - 32768;
        int e = w >> 7, v = w & 127;
        g_owt[w] = owg[v * 32 + e];
    }
}

// ---------------------------------------------------------------------------
// Encoder + VQ. One block per batch element.
// ---------------------------------------------------------------------------
constexpr int ENC_SMEM_FLOATS = 4352 + 16384 + 2304 + 16384 + 1952 + 640 + 16
                              + 192 + 32 + 128 + 32;
constexpr int ENC_SMEM_BYTES = ENC_SMEM_FLOATS * 4;

__global__ void __launch_bounds__(512, 1)
enc_kernel(const int* __restrict__ tidx,
           const float* __restrict__ b1g, const float* __restrict__ b2g,
           const float* __restrict__ b3g, const float* __restrict__ cbg)
{
    extern __shared__ float sm[];
    float* s_h1  = sm;                  // 64 x 68, idx = o*68 + (pos+1)
    float* s_w2t = s_h1 + 4352;         // [i][o][k4]  16384
    float* s_h2  = s_w2t + 16384;       // 64 x 36 (idx o*36 + t)
    float* s_w3t = s_h2 + 2304;         // [i][d][k4]  16384
    float* s_enc = s_w3t + 16384;       // 30 x 65
    float* s_cb  = s_enc + 1952;        // 10 x 64
    float* s_c2  = s_cb + 640;          // 16
    float* s_b1  = s_c2 + 16;
    float* s_b2  = s_b1 + 64;
    float* s_b3  = s_b2 + 64;
    float* s_lp  = s_b3 + 64;           // 32
    int*   s_tok = (int*)(s_lp + 32);   // 128
    int*   s_code = s_tok + 128;        // 32

    const int tid = threadIdx.x;
    const int b = blockIdx.x;

    // ---- stage A ----
    if (tid < 128) s_tok[tid] = tidx[b * 128 + tid];
    {
        float4* dst = (float4*)s_w2t; const float4* src = (const float4*)g_w2p;
        for (int u = tid; u < 4096; u += 512) dst[u] = src[u];
    }
    {
        float4* dst = (float4*)s_w3t; const float4* src = (const float4*)g_w3p;
        for (int u = tid; u < 4096; u += 512) dst[u] = src[u];
    }
    for (int u = tid; u < 640; u += 512) s_cb[u] = cbg[u];
    if (tid < 64) { s_b1[tid] = b1g[tid]; s_b2[tid] = b2g[tid]; s_b3[tid] = b3g[tid]; }
    for (int u = tid; u < 4352; u += 512) s_h1[u] = 0.f;
    __syncthreads();

    if (tid < NC_) {
        float s = 0.f;
#pragma unroll
        for (int d = 0; d < 64; d++) { float c = s_cb[tid * 64 + d]; s += c * c; }
        s_c2[tid] = s;
    }

    // ---- conv1 (k3 s2 p1) via folded embedding + ReLU ----
    {
        int o = tid & 63, g = tid >> 6;
        float bb = s_b1[o];
#pragma unroll
        for (int j = 0; j < 8; j++) {
            int t = g * 8 + j;
            int p0 = 2 * t - 1;
            float acc = bb;
            if (p0 >= 0) acc += g_proj1[(s_tok[p0] * 3 + 0) * 64 + o];
            acc += g_proj1[(s_tok[p0 + 1] * 3 + 1) * 64 + o];
            acc += g_proj1[(s_tok[p0 + 2] * 3 + 2) * 64 + o];
            s_h1[o * 68 + t + 1] = fmaxf(acc, 0.f);
        }
    }
    __syncthreads();

    // ---- conv2 (64->64, k3 s2 p1) + ReLU ----
    {
        int o = tid & 63, g = tid >> 6;
        int tb = g * 4;
        float bb = s_b2[o];
        float a0 = bb, a1 = bb, a2 = bb, a3 = bb;
#pragma unroll 4
        for (int i = 0; i < 64; i++) {
            const float* hr = s_h1 + i * 68 + 2 * tb;   // 16B aligned (8g)
            float4 hA = *(const float4*)(hr);
            float4 hB = *(const float4*)(hr + 4);
            float  h8 = hr[8];
            float4 wv = *(const float4*)(s_w2t + ((i << 6) + o) * 4);
            float w0 = wv.x, w1 = wv.y, w2 = wv.z;
            a0 += w0 * hA.x + w1 * hA.y + w2 * hA.z;
            a1 += w0 * hA.z + w1 * hA.w + w2 * hB.x;
            a2 += w0 * hB.x + w1 * hB.y + w2 * hB.z;
            a3 += w0 * hB.z + w1 * hB.w + w2 * h8;
        }
        s_h2[o * 36 + tb + 0] = fmaxf(a0, 0.f);
        s_h2[o * 36 + tb + 1] = fmaxf(a1, 0.f);
        s_h2[o * 36 + tb + 2] = fmaxf(a2, 0.f);
        s_h2[o * 36 + tb + 3] = fmaxf(a3, 0.f);
        if (g == 7) {   // zero the 4 pad columns so conv3's vector reads see 0
            s_h2[o * 36 + 32] = 0.f;
            s_h2[o * 36 + 33] = 0.f;
            s_h2[o * 36 + 34] = 0.f;
            s_h2[o * 36 + 35] = 0.f;
        }
    }
    __syncthreads();

    // ---- conv3 (64->D, k3 s1 p0), no relu ----
    {
        int d = tid & 63, g = tid >> 6;
        int tb = g * 4;
        float bb = s_b3[d];
        float a0 = bb, a1 = bb, a2 = bb, a3 = bb;
#pragma unroll 4
        for (int i = 0; i < 64; i++) {
            const float* hr = s_h2 + i * 36 + tb;       // 16B aligned (4g)
            float4 hA = *(const float4*)(hr);
            float2 hB = *(const float2*)(hr + 4);
            float4 wv = *(const float4*)(s_w3t + ((i << 6) + d) * 4);
            float w0 = wv.x, w1 = wv.y, w2 = wv.z;
            a0 += w0 * hA.x + w1 * hA.y + w2 * hA.z;
            a1 += w0 * hA.y + w1 * hA.z + w2 * hA.w;
            a2 += w0 * hA.z + w1 * hA.w + w2 * hB.x;
            a3 += w0 * hA.w + w1 * hB.x + w2 * hB.y;
        }
        if (tb + 0 < 30) s_enc[(tb + 0) * 65 + d] = a0;
        if (tb + 1 < 30) s_enc[(tb + 1) * 65 + d] = a1;
        if (tb + 2 < 30) s_enc[(tb + 2) * 65 + d] = a2;
        if (tb + 3 < 30) s_enc[(tb + 3) * 65 + d] = a3;
    }
    __syncthreads();

    // ---- VQ ----
    if (tid < 30) {
        const float* f = s_enc + tid * 65;
        float f2 = 0.f;
#pragma unroll
        for (int d = 0; d < 64; d++) f2 += f[d] * f[d];
        float best = 3.4e38f; int bc = 0;
        for (int c = 0; c < NC_; c++) {
            const float* cr = s_cb + c * 64;
            float dot = 0.f;
#pragma unroll
            for (int d = 0; d < 64; d++) dot += f[d] * cr[d];
            float d2 = f2 - 2.f * dot + s_c2[c];
            if (d2 < best) { best = d2; bc = c; }
        }
        s_code[tid] = bc;
        const float* cr = s_cb + bc * 64;
        float ls = 0.f;
#pragma unroll
        for (int d = 0; d < 64; d++) { float df = f[d] - cr[d]; ls += df * df; }
        s_lp[tid] = ls;
        g_codes[b * 32 + tid] = bc;
    }
    __syncthreads();
    if (tid == 0) {
        float s = 0.f;
        for (int i = 0; i < 30; i++) s += s_lp[i];
        g_loss[b] = s;
    }

    // ---- enc features -> contiguous scratch [30][64] ----
    {
        float* ge = g_enc + (long long)b * 1920;
        for (int u = tid; u < 1920; u += 512)
            ge[u] = s_enc[(u >> 6) * 65 + (u & 63)];
    }
}

// ---------------------------------------------------------------------------
// Broadcast fan-out (memory-roofline bound)
// ---------------------------------------------------------------------------
__global__ void __launch_bounds__(256)
bcast_kernel(const float* __restrict__ cbg, float* __restrict__ out)
{
    __shared__ float4 s_enc4[480];
    __shared__ float4 s_cb4[160];
    __shared__ int    s_code[32];

    const int tid = threadIdx.x;
    const int b = blockIdx.x;

    {
        const float4* ge4 = (const float4*)(g_enc + (long long)b * 1920);
        for (int u = tid; u < 480; u += 256) s_enc4[u] = ge4[u];
        const float4* cb4 = (const float4*)cbg;
        if (tid < 160) s_cb4[tid] = cb4[tid];
        if (tid < 30) s_code[tid] = g_codes[b * 32 + tid];
    }
    __syncthreads();

    const int d4 = tid & 15;
    const int jr = tid >> 4;
    float4* feat4  = (float4*)(out + OFF_FEAT  + (long long)b * 57600);
    float4* quant4 = (float4*)(out + OFF_QUANT + (long long)b * 57600);

#pragma unroll 2
    for (int i = 0; i < 30; i++) {
        float4 fv = s_enc4[i * 16 + d4];
        float4 qv = s_cb4[s_code[i] * 16 + d4];
        int base = i * 480;
        feat4 [base + jr * 16 + d4] = fv;
        quant4[base + jr * 16 + d4] = qv;
        if (jr + 16 < 30) {
            feat4 [base + (jr + 16) * 16 + d4] = fv;
            quant4[base + (jr + 16) * 16 + d4] = qv;
        }
    }

    float* puz = out + OFF_PUZ + (long long)b * 900;
    for (int u = tid; u < 900; u += 256)
        puz[u] = (float)s_code[u / 30];
}

// ---------------------------------------------------------------------------
// Decoder + output projection. One block per batch element.
// ---------------------------------------------------------------------------
constexpr int DEC_SMEM_FLOATS = 1920 + 2304 + 16384 + 4352 + 8192 + 4224 + 4096
                              + 288 + 32;
constexpr int DEC_SMEM_BYTES = DEC_SMEM_FLOATS * 4;

__global__ void __launch_bounds__(512, 1)
dec_kernel(const float* __restrict__ b1g,
           const float* __restrict__ w2g, const float* __restrict__ b2g,
           const float* __restrict__ w3g, const float* __restrict__ b3g,
           const float* __restrict__ obg,
           float* __restrict__ out)
{
    extern __shared__ float sm[];
    float* s_P1  = sm;                    // 1920
    float* s_h1p = s_P1 + 1920;           // 64 x 36 (idx o*36 + s+1)
    float* s_w2t = s_h1p + 2304;          // [d][o][k4] 16384
    float* s_h2p = s_w2t + 16384;         // 64 x 68 (idx o*68 + t+1)
    float* s_w3t = s_h2p + 4352;          // [d][e][k4] 8192
    float* s_dec = s_w3t + 8192;          // 32 x 132
    float* s_owt = s_dec + 4224;          // [e][v] 4096
    float* s_b1  = s_owt + 4096;
    float* s_b2  = s_b1 + 64;
    float* s_b3  = s_b2 + 64;
    float* s_ob  = s_b3 + 32;
    int*   s_code = (int*)(s_ob + 128);

    const int tid = threadIdx.x;
    const int b = blockIdx.x;

    for (int u = tid; u < 1920; u += 512) s_P1[u] = g_P1[u];
    if (tid < 30) s_code[tid] = g_codes[b * 32 + tid];
    {
        float4* dst = (float4*)s_w2t; const float4* src = (const float4*)w2g;
        for (int u = tid; u < 4096; u += 512) dst[u] = src[u];
    }
    {
        float4* dst = (float4*)s_w3t; const float4* src = (const float4*)w3g;
        for (int u = tid; u < 2048; u += 512) dst[u] = src[u];
    }
    {
        float4* dst = (float4*)s_owt; const float4* src = (const float4*)g_owt;
        for (int u = tid; u < 1024; u += 512) dst[u] = src[u];
    }
    if (tid < 64) { s_b1[tid] = b1g[tid]; s_b2[tid] = b2g[tid]; }
    if (tid < 32) s_b3[tid] = b3g[tid];
    if (tid < 128) s_ob[tid] = obg[tid];
    for (int u = tid; u < 2304; u += 512) s_h1p[u] = 0.f;
    for (int u = tid; u < 4352; u += 512) s_h2p[u] = 0.f;
    __syncthreads();

    // ---- convT1 (s1 p0 k3) via folded codebook + ReLU ----
    {
        int o = tid & 63, g = tid >> 6;
        float bb = s_b1[o];
#pragma unroll
        for (int j = 0; j < 4; j++) {
            int t = g * 4 + j;
            float acc = bb;
#pragma unroll
            for (int k = 0; k < 3; k++) {
                int s = t - k;
                if (s >= 0 && s < 30)
                    acc += s_P1[(s_code[s] * 3 + k) * 64 + o];
            }
            s_h1p[o * 36 + t + 1] = fmaxf(acc, 0.f);
        }
    }
    __syncthreads();

    // ---- convT2 (s2 p1 k4) + ReLU : out [64][64] ----
    {
        int o = tid & 63, g = tid >> 6;
        int tb = g * 8;
        float bb = s_b2[o];
        float acc[8];
#pragma unroll
        for (int j = 0; j < 8; j++) acc[j] = bb;
#pragma unroll 2
        for (int d = 0; d < 64; d++) {
            float4 wv = *(const float4*)(s_w2t + ((d << 6) + o) * 4);
            float w0 = wv.x, w1 = wv.y, w2 = wv.z, w3 = wv.w;
            const float* hr = s_h1p + d * 36 + 4 * g;   // 16B aligned
            float4 lA = *(const float4*)(hr);
            float2 lB = *(const float2*)(hr + 4);
            float l0 = lA.x, l1 = lA.y, l2 = lA.z, l3 = lA.w, l4 = lB.x, l5 = lB.y;
            acc[0] += w1 * l1 + w3 * l0;
            acc[2] += w1 * l2 + w3 * l1;
            acc[4] += w1 * l3 + w3 * l2;
            acc[6] += w1 * l4 + w3 * l3;
            acc[1] += w0 * l2 + w2 * l1;
            acc[3] += w0 * l3 + w2 * l2;
            acc[5] += w0 * l4 + w2 * l3;
            acc[7] += w0 * l5 + w2 * l4;
        }
#pragma unroll
        for (int j = 0; j < 8; j++)
            s_h2p[o * 68 + tb + j + 1] = fmaxf(acc[j], 0.f);
    }
    __syncthreads();

    // ---- convT3 (s2 p1 k4) : out [32][128], +b3, no relu ----
    {
        int e = tid & 31, g = tid >> 5;
        int lb = g * 8;
        float bb = s_b3[e];
        float acc[8];
#pragma unroll
        for (int j = 0; j < 8; j++) acc[j] = bb;
#pragma unroll 2
        for (int d = 0; d < 64; d++) {
            float4 wv = *(const float4*)(s_w3t + ((d << 5) + e) * 4);
            float w0 = wv.x, w1 = wv.y, w2 = wv.z, w3 = wv.w;
            const float* hr = s_h2p + d * 68 + 4 * g;   // 16B aligned
            float4 lA = *(const float4*)(hr);
            float2 lB = *(const float2*)(hr + 4);
            float l0 = lA.x, l1 = lA.y, l2 = lA.z, l3 = lA.w, l4 = lB.x, l5 = lB.y;
            acc[0] += w1 * l1 + w3 * l0;
            acc[2] += w1 * l2 + w3 * l1;
            acc[4] += w1 * l3 + w3 * l2;
            acc[6] += w1 * l4 + w3 * l3;
            acc[1] += w0 * l2 + w2 * l1;
            acc[3] += w0 * l3 + w2 * l2;
            acc[5] += w0 * l4 + w2 * l3;
            acc[7] += w0 * l5 + w2 * l4;
        }
#pragma unroll
        for (int j = 0; j < 8; j++)
            s_dec[e * 132 + lb + j] = acc[j];
    }
    __syncthreads();

    // ---- projection: logits[l][v] = sum_e dec[e][l]*out_w[v][e] + out_b[v] ----
    {
        int v0 = tid & 63, g = tid >> 6;
        int lb = g * 16;
        float a0[16], a1[16];
#pragma unroll
        for (int j = 0; j < 16; j++) { a0[j] = 0.f; a1[j] = 0.f; }
#pragma unroll 4
        for (int e = 0; e < 32; e++) {
            float wv0 = s_owt[e * 128 + v0];
            float wv1 = s_owt[e * 128 + v0 + 64];
            const float4* dr4 = (const float4*)(s_dec + e * 132 + lb);
            float dl[16];
            *(float4*)(dl + 0)  = dr4[0];
            *(float4*)(dl + 4)  = dr4[1];
            *(float4*)(dl + 8)  = dr4[2];
            *(float4*)(dl + 12) = dr4[3];
#pragma unroll
            for (int j = 0; j < 16; j++) {
                a0[j] += wv0 * dl[j];
                a1[j] += wv1 * dl[j];
            }
        }
        float* lg = out + (long long)b * (128 * 128);
        float ob0 = s_ob[v0], ob1 = s_ob[v0 + 64];
#pragma unroll
        for (int j = 0; j < 16; j++) {
            lg[(lb + j) * 128 + v0]      = a0[j] + ob0;
            lg[(lb + j) * 128 + v0 + 64] = a1[j] + ob1;
        }
    }
}

// ---------------------------------------------------------------------------
__global__ void loss_kernel(float* __restrict__ out)
{
    __shared__ float red[256];
    int tid = threadIdx.x;
    float s = 0.f;
    for (int u = tid; u < B_; u += 256) s += g_loss[u];
    red[tid] = s;
    __syncthreads();
    for (int st = 128; st > 0; st >>= 1) {
        if (tid < st) red[tid] += red[tid + st];
        __syncthreads();
    }
    if (tid == 0)
        out[OFF_LOSS] = 1.25f * red[0] / (float)(B_ * 30 * 64);
}

// ---------------------------------------------------------------------------
extern "C" void kernel_launch(void* const* d_in, const int* in_sizes, int n_in,
                              void* d_out, int out_size)
{
    (void)in_sizes; (void)n_in; (void)out_size;
    const int*   tidx = (const int*)d_in[0];
    const float* emb  = (const float*)d_in[1];
    const float* ew1  = (const float*)d_in[2];
    const float* eb1  = (const float*)d_in[3];
    const float* ew2  = (const float*)d_in[4];
    const float* eb2  = (const float*)d_in[5];
    const float* ew3  = (const float*)d_in[6];
    const float* eb3  = (const float*)d_in[7];
    const float* cb   = (const float*)d_in[8];
    const float* dw1  = (const float*)d_in[9];
    const float* db1  = (const float*)d_in[10];
    const float* dw2  = (const float*)d_in[11];
    const float* db2  = (const float*)d_in[12];
    const float* dw3  = (const float*)d_in[13];
    const float* db3  = (const float*)d_in[14];
    const float* ow   = (const float*)d_in[15];
    const float* ob   = (const float*)d_in[16];
    float* out = (float*)d_out;

    cudaFuncSetAttribute(enc_kernel, cudaFuncAttributeMaxDynamicSharedMemorySize,
                         ENC_SMEM_BYTES);
    cudaFuncSetAttribute(dec_kernel, cudaFuncAttributeMaxDynamicSharedMemorySize,
                         DEC_SMEM_BYTES);

    pre1_kernel<<<48, 512>>>(ew1, emb);
    pre2_kernel<<<4, 512>>>(dw1, cb);
    pre3_kernel<<<72, 512>>>(ew2, ew3, ow);
    enc_kernel<<<B_, 512, ENC_SMEM_BYTES>>>(tidx, eb1, eb2, eb3, cb);
    bcast_kernel<<<B_, 256>>>(cb, out);
    dec_kernel<<<B_, 512, DEC_SMEM_BYTES>>>(db1, dw2, db2, dw3, db3, ob, out);
    loss_kernel<<<1, 256>>>(out);
}

// round 6
// speedup vs baseline: 1.2560x; 1.0521x over previous
#include <cuda_runtime.h>

// ---------------------------------------------------------------------------
// LanguagePuzzleVAESmall: fused VQ-VAE forward
// B=2048, L=128, V=128, E=32, D=64, NC=10
// ---------------------------------------------------------------------------

constexpr int B_ = 2048, L_ = 128, V_ = 128, E_ = 32, D_ = 64, NC_ = 10;

constexpr long long OFF_PUZ   = (long long)B_ * L_ * V_;
constexpr long long OFF_FEAT  = OFF_PUZ  + (long long)B_ * 30 * 30;
constexpr long long OFF_QUANT = OFF_FEAT + (long long)B_ * 900 * 64;
constexpr long long OFF_LOSS  = OFF_QUANT + (long long)B_ * 900 * 64;

// scratch (device globals: no runtime allocation allowed)
__device__ float g_proj1[V_ * 3 * 64];   // conv1 folded into embedding: [v][k][o]
__device__ float g_P1[NC_ * 3 * 64];     // convT1 folded into codebook: [c][k][o]
__device__ float g_w2p[64 * 64 * 4];     // enc_w2 packed [i][o][k4]
__device__ float g_w3p[64 * 64 * 4];     // enc_w3 packed [i][d][k4]
__device__ float g_owt[32 * 128];        // out_w packed [e][v]
__device__ int   g_codes[B_ * 32];
__device__ float g_loss[B_];
__device__ float g_enc[(long long)B_ * 1920];   // [b][i=30][d=64]

// ---------------------------------------------------------------------------
__global__ void pre1_kernel(const float* __restrict__ enc_w1,
                            const float* __restrict__ emb)
{
    int u = blockIdx.x * blockDim.x + threadIdx.x;
    if (u >= V_ * 3 * 64) return;
    int v = u / 192, r = u % 192, k = r / 64, o = r % 64;
    float s = 0.f;
#pragma unroll
    for (int i = 0; i < 32; i++)
        s += enc_w1[(o * 32 + i) * 3 + k] * emb[v * 32 + i];
    g_proj1[u] = s;
}

__global__ void pre2_kernel(const float* __restrict__ dec_w1,
                            const float* __restrict__ cb)
{
    int u = blockIdx.x * blockDim.x + threadIdx.x;
    if (u >= NC_ * 3 * 64) return;
    int c = u / 192, r = u % 192, k = r / 64, o = r % 64;
    float s = 0.f;
#pragma unroll
    for (int d = 0; d < 64; d++)
        s += dec_w1[(d * 64 + o) * 3 + k] * cb[c * 64 + d];
    g_P1[u] = s;
}

// pack enc_w2/enc_w3 -> [i][ch][k4], out_w -> [e][v]
__global__ void pre3_kernel(const float* __restrict__ w2g,
                            const float* __restrict__ w3g,
                            const float* __restrict__ owg)
{
    int u = blockIdx.x * blockDim.x + threadIdx.x;
    if (u < 16384) {
        int i = u >> 8, o = (u >> 2) & 63, k = u & 3;
        g_w2p[u] = (k < 3) ? w2g[o * 192 + i * 3 + k] : 0.f;
    } else if (u < 32768) {
        int w = u - 16384;
        int i = w >> 8, d = (w >> 2) & 63, k = w & 3;
        g_w3p[w] = (k < 3) ? w3g[d * 192 + i * 3 + k] : 0.f;
    } else if (u < 32768 + 4096) {
        int w = u - 32768;
        int e = w >> 7, v = w & 127;
        g_owt[w] = owg[v * 32 + e];
    }
}

// ---------------------------------------------------------------------------
// Encoder + VQ. One block per batch element.
// ---------------------------------------------------------------------------
constexpr int ENC_SMEM_FLOATS = 4352 + 16384 + 2304 + 16384 + 1952 + 640 + 16
                              + 192 + 32 + 128 + 32;
constexpr int ENC_SMEM_BYTES = ENC_SMEM_FLOATS * 4;

__global__ void __launch_bounds__(512, 1)
enc_kernel(const int* __restrict__ tidx,
           const float* __restrict__ b1g, const float* __restrict__ b2g,
           const float* __restrict__ b3g, const float* __restrict__ cbg)
{
    extern __shared__ float sm[];
    float* s_h1  = sm;                  // 64 x 68, idx = o*68 + (pos+1)
    float* s_w2t = s_h1 + 4352;         // [i][o][k4]  16384
    float* s_h2  = s_w2t + 16384;       // 64 x 36 (idx o*36 + t)
    float* s_w3t = s_h2 + 2304;         // [i][d][k4]  16384
    float* s_enc = s_w3t + 16384;       // 30 x 65
    float* s_cb  = s_enc + 1952;        // 10 x 64
    float* s_c2  = s_cb + 640;          // 16
    float* s_b1  = s_c2 + 16;
    float* s_b2  = s_b1 + 64;
    float* s_b3  = s_b2 + 64;
    float* s_lp  = s_b3 + 64;           // 32
    int*   s_tok = (int*)(s_lp + 32);   // 128
    int*   s_code = s_tok + 128;        // 32

    const int tid = threadIdx.x;
    const int b = blockIdx.x;

    // ---- stage A ----
    if (tid < 128) s_tok[tid] = tidx[b * 128 + tid];
    {
        float4* dst = (float4*)s_w2t; const float4* src = (const float4*)g_w2p;
        for (int u = tid; u < 4096; u += 512) dst[u] = src[u];
    }
    {
        float4* dst = (float4*)s_w3t; const float4* src = (const float4*)g_w3p;
        for (int u = tid; u < 4096; u += 512) dst[u] = src[u];
    }
    for (int u = tid; u < 640; u += 512) s_cb[u] = cbg[u];
    if (tid < 64) { s_b1[tid] = b1g[tid]; s_b2[tid] = b2g[tid]; s_b3[tid] = b3g[tid]; }
    for (int u = tid; u < 4352; u += 512) s_h1[u] = 0.f;
    __syncthreads();

    if (tid < NC_) {
        float s = 0.f;
#pragma unroll
        for (int d = 0; d < 64; d++) { float c = s_cb[tid * 64 + d]; s += c * c; }
        s_c2[tid] = s;
    }

    // ---- conv1 (k3 s2 p1) via folded embedding + ReLU ----
    {
        int o = tid & 63, g = tid >> 6;
        float bb = s_b1[o];
#pragma unroll
        for (int j = 0; j < 8; j++) {
            int t = g * 8 + j;
            int p0 = 2 * t - 1;
            float acc = bb;
            if (p0 >= 0) acc += g_proj1[(s_tok[p0] * 3 + 0) * 64 + o];
            acc += g_proj1[(s_tok[p0 + 1] * 3 + 1) * 64 + o];
            acc += g_proj1[(s_tok[p0 + 2] * 3 + 2) * 64 + o];
            s_h1[o * 68 + t + 1] = fmaxf(acc, 0.f);
        }
    }
    __syncthreads();

    // ---- conv2 (64->64, k3 s2 p1) + ReLU ----
    {
        int o = tid & 63, g = tid >> 6;
        int tb = g * 4;
        float bb = s_b2[o];
        float a0 = bb, a1 = bb, a2 = bb, a3 = bb;
#pragma unroll 4
        for (int i = 0; i < 64; i++) {
            const float* hr = s_h1 + i * 68 + 2 * tb;   // 16B aligned (8g)
            float4 hA = *(const float4*)(hr);
            float4 hB = *(const float4*)(hr + 4);
            float  h8 = hr[8];
            float4 wv = *(const float4*)(s_w2t + ((i << 6) + o) * 4);
            float w0 = wv.x, w1 = wv.y, w2 = wv.z;
            a0 += w0 * hA.x + w1 * hA.y + w2 * hA.z;
            a1 += w0 * hA.z + w1 * hA.w + w2 * hB.x;
            a2 += w0 * hB.x + w1 * hB.y + w2 * hB.z;
            a3 += w0 * hB.z + w1 * hB.w + w2 * h8;
        }
        s_h2[o * 36 + tb + 0] = fmaxf(a0, 0.f);
        s_h2[o * 36 + tb + 1] = fmaxf(a1, 0.f);
        s_h2[o * 36 + tb + 2] = fmaxf(a2, 0.f);
        s_h2[o * 36 + tb + 3] = fmaxf(a3, 0.f);
        if (g == 7) {   // zero the 4 pad columns so conv3's vector reads see 0
            s_h2[o * 36 + 32] = 0.f;
            s_h2[o * 36 + 33] = 0.f;
            s_h2[o * 36 + 34] = 0.f;
            s_h2[o * 36 + 35] = 0.f;
        }
    }
    __syncthreads();

    // ---- conv3 (64->D, k3 s1 p0), no relu ----
    {
        int d = tid & 63, g = tid >> 6;
        int tb = g * 4;
        float bb = s_b3[d];
        float a0 = bb, a1 = bb, a2 = bb, a3 = bb;
#pragma unroll 4
        for (int i = 0; i < 64; i++) {
            const float* hr = s_h2 + i * 36 + tb;       // 16B aligned (4g)
            float4 hA = *(const float4*)(hr);
            float2 hB = *(const float2*)(hr + 4);
            float4 wv = *(const float4*)(s_w3t + ((i << 6) + d) * 4);
            float w0 = wv.x, w1 = wv.y, w2 = wv.z;
            a0 += w0 * hA.x + w1 * hA.y + w2 * hA.z;
            a1 += w0 * hA.y + w1 * hA.z + w2 * hA.w;
            a2 += w0 * hA.z + w1 * hA.w + w2 * hB.x;
            a3 += w0 * hA.w + w1 * hB.x + w2 * hB.y;
        }
        if (tb + 0 < 30) s_enc[(tb + 0) * 65 + d] = a0;
        if (tb + 1 < 30) s_enc[(tb + 1) * 65 + d] = a1;
        if (tb + 2 < 30) s_enc[(tb + 2) * 65 + d] = a2;
        if (tb + 3 < 30) s_enc[(tb + 3) * 65 + d] = a3;
    }
    __syncthreads();

    // ---- VQ ----
    if (tid < 30) {
        const float* f = s_enc + tid * 65;
        float f2 = 0.f;
#pragma unroll
        for (int d = 0; d < 64; d++) f2 += f[d] * f[d];
        float best = 3.4e38f; int bc = 0;
        for (int c = 0; c < NC_; c++) {
            const float* cr = s_cb + c * 64;
            float dot = 0.f;
#pragma unroll
            for (int d = 0; d < 64; d++) dot += f[d] * cr[d];
            float d2 = f2 - 2.f * dot + s_c2[c];
            if (d2 < best) { best = d2; bc = c; }
        }
        s_code[tid] = bc;
        const float* cr = s_cb + bc * 64;
        float ls = 0.f;
#pragma unroll
        for (int d = 0; d < 64; d++) { float df = f[d] - cr[d]; ls += df * df; }
        s_lp[tid] = ls;
        g_codes[b * 32 + tid] = bc;
    }
    __syncthreads();
    if (tid == 0) {
        float s = 0.f;
        for (int i = 0; i < 30; i++) s += s_lp[i];
        g_loss[b] = s;
    }

    // ---- enc features -> contiguous scratch [30][64] ----
    {
        float* ge = g_enc + (long long)b * 1920;
        for (int u = tid; u < 1920; u += 512)
            ge[u] = s_enc[(u >> 6) * 65 + (u & 63)];
    }
}

// ---------------------------------------------------------------------------
// Decoder + output projection + fused broadcast fan-out.
// One block per batch element. The 944 MB feat/quant fan-out is issued in the
// prologue (fire-and-forget STG.128) and drains behind the convT compute.
// ---------------------------------------------------------------------------
constexpr int DEC_SMEM_FLOATS = 2560   // s_enc4 (1920) + s_cb4 (640)
                              + 1920 + 2304 + 16384 + 4352 + 8192 + 4224 + 4096
                              + 288 + 32;
constexpr int DEC_SMEM_BYTES = DEC_SMEM_FLOATS * 4;

__global__ void __launch_bounds__(512, 1)
dec_kernel(const float* __restrict__ cbg, const float* __restrict__ b1g,
           const float* __restrict__ w2g, const float* __restrict__ b2g,
           const float* __restrict__ w3g, const float* __restrict__ b3g,
           const float* __restrict__ obg,
           float* __restrict__ out)
{
    extern __shared__ float sm[];
    float4* s_enc4 = (float4*)sm;          // 480 float4  (16B aligned)
    float4* s_cb4  = s_enc4 + 480;         // 160 float4
    float* s_P1  = sm + 2560;              // 1920
    float* s_h1p = s_P1 + 1920;            // 64 x 36 (idx o*36 + s+1)
    float* s_w2t = s_h1p + 2304;           // [d][o][k4] 16384
    float* s_h2p = s_w2t + 16384;          // 64 x 68 (idx o*68 + t+1)
    float* s_w3t = s_h2p + 4352;           // [d][e][k4] 8192
    float* s_dec = s_w3t + 8192;           // 32 x 132
    float* s_owt = s_dec + 4224;           // [e][v] 4096
    float* s_b1  = s_owt + 4096;
    float* s_b2  = s_b1 + 64;
    float* s_b3  = s_b2 + 64;
    float* s_ob  = s_b3 + 32;
    int*   s_code = (int*)(s_ob + 128);

    const int tid = threadIdx.x;
    const int b = blockIdx.x;

    // ---- staging ----
    {
        const float4* ge4 = (const float4*)(g_enc + (long long)b * 1920);
        if (tid < 480) s_enc4[tid] = ge4[tid];
        const float4* cb4 = (const float4*)cbg;
        if (tid >= 480 && tid - 480 < 32) { /* spread */ }
        if (tid < 160) s_cb4[tid] = cb4[tid];   // codebook (also used for quant stores)
    }
    for (int u = tid; u < 1920; u += 512) s_P1[u] = g_P1[u];
    if (tid < 30) s_code[tid] = g_codes[b * 32 + tid];
    {
        float4* dst = (float4*)s_w2t; const float4* src = (const float4*)w2g;
        for (int u = tid; u < 4096; u += 512) dst[u] = src[u];
    }
    {
        float4* dst = (float4*)s_w3t; const float4* src = (const float4*)w3g;
        for (int u = tid; u < 2048; u += 512) dst[u] = src[u];
    }
    {
        float4* dst = (float4*)s_owt; const float4* src = (const float4*)g_owt;
        for (int u = tid; u < 1024; u += 512) dst[u] = src[u];
    }
    if (tid < 64) { s_b1[tid] = b1g[tid]; s_b2[tid] = b2g[tid]; }
    if (tid < 32) s_b3[tid] = b3g[tid];
    if (tid < 128) s_ob[tid] = obg[tid];
    for (int u = tid; u < 2304; u += 512) s_h1p[u] = 0.f;
    for (int u = tid; u < 4352; u += 512) s_h2p[u] = 0.f;
    __syncthreads();

    // ---- fused broadcast fan-out: features / quantized_st / puzzles ----
    // Fire-and-forget stores; they drain behind the convT compute below.
    {
        const int d4 = tid & 15;
        const int jr = tid >> 4;            // 0..31
        float4* feat4  = (float4*)(out + OFF_FEAT  + (long long)b * 57600);
        float4* quant4 = (float4*)(out + OFF_QUANT + (long long)b * 57600);
        if (jr < 30) {
#pragma unroll 2
            for (int i = 0; i < 30; i++) {
                float4 fv = s_enc4[i * 16 + d4];
                float4 qv = s_cb4[s_code[i] * 16 + d4];
                int idx = i * 480 + jr * 16 + d4;
                feat4[idx]  = fv;
                quant4[idx] = qv;
            }
        }
        float* puz = out + OFF_PUZ + (long long)b * 900;
        for (int u = tid; u < 900; u += 512)
            puz[u] = (float)s_code[u / 30];
    }

    // ---- convT1 (s1 p0 k3) via folded codebook + ReLU ----
    {
        int o = tid & 63, g = tid >> 6;
        float bb = s_b1[o];
#pragma unroll
        for (int j = 0; j < 4; j++) {
            int t = g * 4 + j;
            float acc = bb;
#pragma unroll
            for (int k = 0; k < 3; k++) {
                int s = t - k;
                if (s >= 0 && s < 30)
                    acc += s_P1[(s_code[s] * 3 + k) * 64 + o];
            }
            s_h1p[o * 36 + t + 1] = fmaxf(acc, 0.f);
        }
    }
    __syncthreads();

    // ---- convT2 (s2 p1 k4) + ReLU : out [64][64] ----
    {
        int o = tid & 63, g = tid >> 6;
        int tb = g * 8;
        float bb = s_b2[o];
        float acc[8];
#pragma unroll
        for (int j = 0; j < 8; j++) acc[j] = bb;
#pragma unroll 2
        for (int d = 0; d < 64; d++) {
            float4 wv = *(const float4*)(s_w2t + ((d << 6) + o) * 4);
            float w0 = wv.x, w1 = wv.y, w2 = wv.z, w3 = wv.w;
            const float* hr = s_h1p + d * 36 + 4 * g;   // 16B aligned
            float4 lA = *(const float4*)(hr);
            float2 lB = *(const float2*)(hr + 4);
            float l0 = lA.x, l1 = lA.y, l2 = lA.z, l3 = lA.w, l4 = lB.x, l5 = lB.y;
            acc[0] += w1 * l1 + w3 * l0;
            acc[2] += w1 * l2 + w3 * l1;
            acc[4] += w1 * l3 + w3 * l2;
            acc[6] += w1 * l4 + w3 * l3;
            acc[1] += w0 * l2 + w2 * l1;
            acc[3] += w0 * l3 + w2 * l2;
            acc[5] += w0 * l4 + w2 * l3;
            acc[7] += w0 * l5 + w2 * l4;
        }
#pragma unroll
        for (int j = 0; j < 8; j++)
            s_h2p[o * 68 + tb + j + 1] = fmaxf(acc[j], 0.f);
    }
    __syncthreads();

    // ---- convT3 (s2 p1 k4) : out [32][128], +b3, no relu ----
    {
        int e = tid & 31, g = tid >> 5;
        int lb = g * 8;
        float bb = s_b3[e];
        float acc[8];
#pragma unroll
        for (int j = 0; j < 8; j++) acc[j] = bb;
#pragma unroll 2
        for (int d = 0; d < 64; d++) {
            float4 wv = *(const float4*)(s_w3t + ((d << 5) + e) * 4);
            float w0 = wv.x, w1 = wv.y, w2 = wv.z, w3 = wv.w;
            const float* hr = s_h2p + d * 68 + 4 * g;   // 16B aligned
            float4 lA = *(const float4*)(hr);
            float2 lB = *(const float2*)(hr + 4);
            float l0 = lA.x, l1 = lA.y, l2 = lA.z, l3 = lA.w, l4 = lB.x, l5 = lB.y;
            acc[0] += w1 * l1 + w3 * l0;
            acc[2] += w1 * l2 + w3 * l1;
            acc[4] += w1 * l3 + w3 * l2;
            acc[6] += w1 * l4 + w3 * l3;
            acc[1] += w0 * l2 + w2 * l1;
            acc[3] += w0 * l3 + w2 * l2;
            acc[5] += w0 * l4 + w2 * l3;
            acc[7] += w0 * l5 + w2 * l4;
        }
#pragma unroll
        for (int j = 0; j < 8; j++)
            s_dec[e * 132 + lb + j] = acc[j];
    }
    __syncthreads();

    // ---- projection: logits[l][v] = sum_e dec[e][l]*out_w[v][e] + out_b[v] ----
    {
        int v0 = tid & 63, g = tid >> 6;
        int lb = g * 16;
        float a0[16], a1[16];
#pragma unroll
        for (int j = 0; j < 16; j++) { a0[j] = 0.f; a1[j] = 0.f; }
#pragma unroll 4
        for (int e = 0; e < 32; e++) {
            float wv0 = s_owt[e * 128 + v0];
            float wv1 = s_owt[e * 128 + v0 + 64];
            const float4* dr4 = (const float4*)(s_dec + e * 132 + lb);
            float dl[16];
            *(float4*)(dl + 0)  = dr4[0];
            *(float4*)(dl + 4)  = dr4[1];
            *(float4*)(dl + 8)  = dr4[2];
            *(float4*)(dl + 12) = dr4[3];
#pragma unroll
            for (int j = 0; j < 16; j++) {
                a0[j] += wv0 * dl[j];
                a1[j] += wv1 * dl[j];
            }
        }
        float* lg = out + (long long)b * (128 * 128);
        float ob0 = s_ob[v0], ob1 = s_ob[v0 + 64];
#pragma unroll
        for (int j = 0; j < 16; j++) {
            lg[(lb + j) * 128 + v0]      = a0[j] + ob0;
            lg[(lb + j) * 128 + v0 + 64] = a1[j] + ob1;
        }
    }
}

// ---------------------------------------------------------------------------
__global__ void loss_kernel(float* __restrict__ out)
{
    __shared__ float red[256];
    int tid = threadIdx.x;
    float s = 0.f;
    for (int u = tid; u < B_; u += 256) s += g_loss[u];
    red[tid] = s;
    __syncthreads();
    for (int st = 128; st > 0; st >>= 1) {
        if (tid < st) red[tid] += red[tid + st];
        __syncthreads();
    }
    if (tid == 0)
        out[OFF_LOSS] = 1.25f * red[0] / (float)(B_ * 30 * 64);
}

// ---------------------------------------------------------------------------
extern "C" void kernel_launch(void* const* d_in, const int* in_sizes, int n_in,
                              void* d_out, int out_size)
{
    (void)in_sizes; (void)n_in; (void)out_size;
    const int*   tidx = (const int*)d_in[0];
    const float* emb  = (const float*)d_in[1];
    const float* ew1  = (const float*)d_in[2];
    const float* eb1  = (const float*)d_in[3];
    const float* ew2  = (const float*)d_in[4];
    const float* eb2  = (const float*)d_in[5];
    const float* ew3  = (const float*)d_in[6];
    const float* eb3  = (const float*)d_in[7];
    const float* cb   = (const float*)d_in[8];
    const float* dw1  = (const float*)d_in[9];
    const float* db1  = (const float*)d_in[10];
    const float* dw2  = (const float*)d_in[11];
    const float* db2  = (const float*)d_in[12];
    const float* dw3  = (const float*)d_in[13];
    const float* db3  = (const float*)d_in[14];
    const float* ow   = (const float*)d_in[15];
    const float* ob   = (const float*)d_in[16];
    float* out = (float*)d_out;

    cudaFuncSetAttribute(enc_kernel, cudaFuncAttributeMaxDynamicSharedMemorySize,
                         ENC_SMEM_BYTES);
    cudaFuncSetAttribute(dec_kernel, cudaFuncAttributeMaxDynamicSharedMemorySize,
                         DEC_SMEM_BYTES);

    pre1_kernel<<<48, 512>>>(ew1, emb);
    pre2_kernel<<<4, 512>>>(dw1, cb);
    pre3_kernel<<<72, 512>>>(ew2, ew3, ow);
    enc_kernel<<<B_, 512, ENC_SMEM_BYTES>>>(tidx, eb1, eb2, eb3, cb);
    dec_kernel<<<B_, 512, DEC_SMEM_BYTES>>>(cb, db1, dw2, db2, dw3, db3, ob, out);
    loss_kernel<<<1, 256>>>(out);
}

// round 7
// speedup vs baseline: 1.3703x; 1.0911x over previous
#include <cuda_runtime.h>

// ---------------------------------------------------------------------------
// LanguagePuzzleVAESmall: fused VQ-VAE forward
// B=2048, L=128, V=128, E=32, D=64, NC=10
// ---------------------------------------------------------------------------

constexpr int B_ = 2048, L_ = 128, V_ = 128, E_ = 32, D_ = 64, NC_ = 10;

constexpr long long OFF_PUZ   = (long long)B_ * L_ * V_;
constexpr long long OFF_FEAT  = OFF_PUZ  + (long long)B_ * 30 * 30;
constexpr long long OFF_QUANT = OFF_FEAT + (long long)B_ * 900 * 64;
constexpr long long OFF_LOSS  = OFF_QUANT + (long long)B_ * 900 * 64;

// scratch (device globals: no runtime allocation allowed)
__device__ float g_proj1[V_ * 3 * 64];   // conv1 folded into embedding: [v][k][o]
__device__ float g_P1[NC_ * 3 * 64];     // convT1 folded into codebook: [c][k][o]
__device__ float g_w2p[64 * 64 * 4];     // enc_w2 packed [i][o][k4]
__device__ float g_w3p[64 * 64 * 4];     // enc_w3 packed [i][d][k4]
__device__ float g_owt[32 * 128];        // out_w packed [e][v]
__device__ int   g_codes[B_ * 32];
__device__ float g_loss[B_];
__device__ float g_enc[(long long)B_ * 1920];   // [b][i=30][d=64]

// ---------------------------------------------------------------------------
__global__ void pre1_kernel(const float* __restrict__ enc_w1,
                            const float* __restrict__ emb)
{
    int u = blockIdx.x * blockDim.x + threadIdx.x;
    if (u >= V_ * 3 * 64) return;
    int v = u / 192, r = u % 192, k = r / 64, o = r % 64;
    float s = 0.f;
#pragma unroll
    for (int i = 0; i < 32; i++)
        s += enc_w1[(o * 32 + i) * 3 + k] * emb[v * 32 + i];
    g_proj1[u] = s;
}

__global__ void pre2_kernel(const float* __restrict__ dec_w1,
                            const float* __restrict__ cb)
{
    int u = blockIdx.x * blockDim.x + threadIdx.x;
    if (u >= NC_ * 3 * 64) return;
    int c = u / 192, r = u % 192, k = r / 64, o = r % 64;
    float s = 0.f;
#pragma unroll
    for (int d = 0; d < 64; d++)
        s += dec_w1[(d * 64 + o) * 3 + k] * cb[c * 64 + d];
    g_P1[u] = s;
}

// pack enc_w2/enc_w3 -> [i][ch][k4], out_w -> [e][v]
__global__ void pre3_kernel(const float* __restrict__ w2g,
                            const float* __restrict__ w3g,
                            const float* __restrict__ owg)
{
    int u = blockIdx.x * blockDim.x + threadIdx.x;
    if (u < 16384) {
        int i = u >> 8, o = (u >> 2) & 63, k = u & 3;
        g_w2p[u] = (k < 3) ? w2g[o * 192 + i * 3 + k] : 0.f;
    } else if (u < 32768) {
        int w = u - 16384;
        int i = w >> 8, d = (w >> 2) & 63, k = w & 3;
        g_w3p[w] = (k < 3) ? w3g[d * 192 + i * 3 + k] : 0.f;
    } else if (u < 32768 + 4096) {
        int w = u - 32768;
        int e = w >> 7, v = w & 127;
        g_owt[w] = owg[v * 32 + e];
    }
}

// ---------------------------------------------------------------------------
// Encoder + VQ. One block per batch element, 2 blocks/SM.
// Weights read through L1 (identical across blocks); smem holds activations only.
// ---------------------------------------------------------------------------
__global__ void __launch_bounds__(512, 2)
enc_kernel(const int* __restrict__ tidx,
           const float* __restrict__ b1g, const float* __restrict__ b2g,
           const float* __restrict__ b3g, const float* __restrict__ cbg)
{
    __shared__ float s_h1[4352];    // 64 x 68, idx = o*68 + (pos+1)
    __shared__ float s_h2[2304];    // 64 x 36
    __shared__ float s_enc[1952];   // 30 x 65
    __shared__ float s_cb[640];     // 10 x 64
    __shared__ float s_c2[16];
    __shared__ float s_lp[32];
    __shared__ int   s_tok[128];
    __shared__ int   s_code[32];

    const int tid = threadIdx.x;
    const int b = blockIdx.x;

    // ---- stage ----
    if (tid < 128) s_tok[tid] = tidx[b * 128 + tid];
    for (int u = tid; u < 640; u += 512) s_cb[u] = cbg[u];
    for (int u = tid; u < 4352; u += 512) s_h1[u] = 0.f;
    __syncthreads();

    if (tid < NC_) {
        float s = 0.f;
#pragma unroll
        for (int d = 0; d < 64; d++) { float c = s_cb[tid * 64 + d]; s += c * c; }
        s_c2[tid] = s;
    }

    // ---- conv1 (k3 s2 p1) via folded embedding + ReLU ----
    {
        int o = tid & 63, g = tid >> 6;
        float bb = __ldg(b1g + o);
#pragma unroll
        for (int j = 0; j < 8; j++) {
            int t = g * 8 + j;
            int p0 = 2 * t - 1;
            float acc = bb;
            if (p0 >= 0) acc += __ldg(g_proj1 + (s_tok[p0] * 3 + 0) * 64 + o);
            acc += __ldg(g_proj1 + (s_tok[p0 + 1] * 3 + 1) * 64 + o);
            acc += __ldg(g_proj1 + (s_tok[p0 + 2] * 3 + 2) * 64 + o);
            s_h1[o * 68 + t + 1] = fmaxf(acc, 0.f);
        }
    }
    __syncthreads();

    // ---- conv2 (64->64, k3 s2 p1) + ReLU ----
    {
        int o = tid & 63, g = tid >> 6;
        int tb = g * 4;
        float bb = __ldg(b2g + o);
        float a0 = bb, a1 = bb, a2 = bb, a3 = bb;
        const float4* wbase = (const float4*)g_w2p + o;
#pragma unroll 4
        for (int i = 0; i < 64; i++) {
            const float* hr = s_h1 + i * 68 + 2 * tb;   // 16B aligned (8g)
            float4 hA = *(const float4*)(hr);
            float4 hB = *(const float4*)(hr + 4);
            float  h8 = hr[8];
            float4 wv = __ldg(wbase + (i << 6));
            float w0 = wv.x, w1 = wv.y, w2 = wv.z;
            a0 += w0 * hA.x + w1 * hA.y + w2 * hA.z;
            a1 += w0 * hA.z + w1 * hA.w + w2 * hB.x;
            a2 += w0 * hB.x + w1 * hB.y + w2 * hB.z;
            a3 += w0 * hB.z + w1 * hB.w + w2 * h8;
        }
        s_h2[o * 36 + tb + 0] = fmaxf(a0, 0.f);
        s_h2[o * 36 + tb + 1] = fmaxf(a1, 0.f);
        s_h2[o * 36 + tb + 2] = fmaxf(a2, 0.f);
        s_h2[o * 36 + tb + 3] = fmaxf(a3, 0.f);
        if (g == 7) {   // zero pad columns for conv3's vector reads
            s_h2[o * 36 + 32] = 0.f;
            s_h2[o * 36 + 33] = 0.f;
            s_h2[o * 36 + 34] = 0.f;
            s_h2[o * 36 + 35] = 0.f;
        }
    }
    __syncthreads();

    // ---- conv3 (64->D, k3 s1 p0), no relu ----
    {
        int d = tid & 63, g = tid >> 6;
        int tb = g * 4;
        float bb = __ldg(b3g + d);
        float a0 = bb, a1 = bb, a2 = bb, a3 = bb;
        const float4* wbase = (const float4*)g_w3p + d;
#pragma unroll 4
        for (int i = 0; i < 64; i++) {
            const float* hr = s_h2 + i * 36 + tb;       // 16B aligned (4g)
            float4 hA = *(const float4*)(hr);
            float2 hB = *(const float2*)(hr + 4);
            float4 wv = __ldg(wbase + (i << 6));
            float w0 = wv.x, w1 = wv.y, w2 = wv.z;
            a0 += w0 * hA.x + w1 * hA.y + w2 * hA.z;
            a1 += w0 * hA.y + w1 * hA.z + w2 * hA.w;
            a2 += w0 * hA.z + w1 * hA.w + w2 * hB.x;
            a3 += w0 * hA.w + w1 * hB.x + w2 * hB.y;
        }
        if (tb + 0 < 30) s_enc[(tb + 0) * 65 + d] = a0;
        if (tb + 1 < 30) s_enc[(tb + 1) * 65 + d] = a1;
        if (tb + 2 < 30) s_enc[(tb + 2) * 65 + d] = a2;
        if (tb + 3 < 30) s_enc[(tb + 3) * 65 + d] = a3;
    }
    __syncthreads();

    // ---- VQ ----
    if (tid < 30) {
        const float* f = s_enc + tid * 65;
        float f2 = 0.f;
#pragma unroll
        for (int d = 0; d < 64; d++) f2 += f[d] * f[d];
        float best = 3.4e38f; int bc = 0;
        for (int c = 0; c < NC_; c++) {
            const float* cr = s_cb + c * 64;
            float dot = 0.f;
#pragma unroll
            for (int d = 0; d < 64; d++) dot += f[d] * cr[d];
            float d2 = f2 - 2.f * dot + s_c2[c];
            if (d2 < best) { best = d2; bc = c; }
        }
        s_code[tid] = bc;
        const float* cr = s_cb + bc * 64;
        float ls = 0.f;
#pragma unroll
        for (int d = 0; d < 64; d++) { float df = f[d] - cr[d]; ls += df * df; }
        s_lp[tid] = ls;
        g_codes[b * 32 + tid] = bc;
    }
    __syncthreads();
    if (tid == 0) {
        float s = 0.f;
        for (int i = 0; i < 30; i++) s += s_lp[i];
        g_loss[b] = s;
    }

    // ---- enc features -> contiguous scratch [30][64] ----
    {
        float* ge = g_enc + (long long)b * 1920;
        for (int u = tid; u < 1920; u += 512)
            ge[u] = s_enc[(u >> 6) * 65 + (u & 63)];
    }
}

// ---------------------------------------------------------------------------
// Decoder + output projection + fused broadcast fan-out.
// One block per batch element, 2 blocks/SM; weights via L1.
// smem floats: enc4 1920 | cb4 640 | h1p 2304 | h2p 4352 | dec 4224 | code 32
// ---------------------------------------------------------------------------
constexpr int DEC_SMEM_FLOATS = 1920 + 640 + 2304 + 4352 + 4224 + 32;
constexpr int DEC_SMEM_BYTES = DEC_SMEM_FLOATS * 4;   // ~53.9 KB

__global__ void __launch_bounds__(512, 2)
dec_kernel(const float* __restrict__ cbg, const float* __restrict__ b1g,
           const float* __restrict__ w2g, const float* __restrict__ b2g,
           const float* __restrict__ w3g, const float* __restrict__ b3g,
           const float* __restrict__ obg,
           float* __restrict__ out)
{
    extern __shared__ float sm[];
    float4* s_enc4 = (float4*)sm;          // 480 float4
    float4* s_cb4  = s_enc4 + 480;         // 160 float4
    float* s_h1p = sm + 2560;              // 64 x 36 (idx o*36 + s+1)
    float* s_h2p = s_h1p + 2304;           // 64 x 68 (idx o*68 + t+1)
    float* s_dec = s_h2p + 4352;           // 32 x 132
    int*   s_code = (int*)(s_dec + 4224);  // 32

    const int tid = threadIdx.x;
    const int b = blockIdx.x;

    // ---- staging (activations + codebook only) ----
    {
        const float4* ge4 = (const float4*)(g_enc + (long long)b * 1920);
        if (tid < 480) s_enc4[tid] = ge4[tid];
        const float4* cb4 = (const float4*)cbg;
        if (tid < 160) s_cb4[tid] = cb4[tid];
        if (tid < 30) s_code[tid] = g_codes[b * 32 + tid];
    }
    for (int u = tid; u < 2304; u += 512) s_h1p[u] = 0.f;
    for (int u = tid; u < 4352; u += 512) s_h2p[u] = 0.f;
    __syncthreads();

    // ---- fused broadcast fan-out: features / quantized_st / puzzles ----
    {
        const int d4 = tid & 15;
        const int jr = tid >> 4;            // 0..31
        float4* feat4  = (float4*)(out + OFF_FEAT  + (long long)b * 57600);
        float4* quant4 = (float4*)(out + OFF_QUANT + (long long)b * 57600);
        if (jr < 30) {
#pragma unroll 2
            for (int i = 0; i < 30; i++) {
                float4 fv = s_enc4[i * 16 + d4];
                float4 qv = s_cb4[s_code[i] * 16 + d4];
                int idx = i * 480 + jr * 16 + d4;
                feat4[idx]  = fv;
                quant4[idx] = qv;
            }
        }
        float* puz = out + OFF_PUZ + (long long)b * 900;
        for (int u = tid; u < 900; u += 512)
            puz[u] = (float)s_code[u / 30];
    }

    // ---- convT1 (s1 p0 k3) via folded codebook + ReLU ----
    {
        int o = tid & 63, g = tid >> 6;
        float bb = __ldg(b1g + o);
#pragma unroll
        for (int j = 0; j < 4; j++) {
            int t = g * 4 + j;
            float acc = bb;
#pragma unroll
            for (int k = 0; k < 3; k++) {
                int s = t - k;
                if (s >= 0 && s < 30)
                    acc += __ldg(g_P1 + (s_code[s] * 3 + k) * 64 + o);
            }
            s_h1p[o * 36 + t + 1] = fmaxf(acc, 0.f);
        }
    }
    __syncthreads();

    // ---- convT2 (s2 p1 k4) + ReLU : out [64][64] ----
    {
        int o = tid & 63, g = tid >> 6;
        int tb = g * 8;
        float bb = __ldg(b2g + o);
        float acc[8];
#pragma unroll
        for (int j = 0; j < 8; j++) acc[j] = bb;
        const float4* wbase = (const float4*)w2g + o;
#pragma unroll 2
        for (int d = 0; d < 64; d++) {
            float4 wv = __ldg(wbase + (d << 6));
            float w0 = wv.x, w1 = wv.y, w2 = wv.z, w3 = wv.w;
            const float* hr = s_h1p + d * 36 + 4 * g;   // 16B aligned
            float4 lA = *(const float4*)(hr);
            float2 lB = *(const float2*)(hr + 4);
            float l0 = lA.x, l1 = lA.y, l2 = lA.z, l3 = lA.w, l4 = lB.x, l5 = lB.y;
            acc[0] += w1 * l1 + w3 * l0;
            acc[2] += w1 * l2 + w3 * l1;
            acc[4] += w1 * l3 + w3 * l2;
            acc[6] += w1 * l4 + w3 * l3;
            acc[1] += w0 * l2 + w2 * l1;
            acc[3] += w0 * l3 + w2 * l2;
            acc[5] += w0 * l4 + w2 * l3;
            acc[7] += w0 * l5 + w2 * l4;
        }
#pragma unroll
        for (int j = 0; j < 8; j++)
            s_h2p[o * 68 + tb + j + 1] = fmaxf(acc[j], 0.f);
    }
    __syncthreads();

    // ---- convT3 (s2 p1 k4) : out [32][128], +b3, no relu ----
    {
        int e = tid & 31, g = tid >> 5;
        int lb = g * 8;
        float bb = __ldg(b3g + e);
        float acc[8];
#pragma unroll
        for (int j = 0; j < 8; j++) acc[j] = bb;
        const float4* wbase = (const float4*)w3g + e;
#pragma unroll 2
        for (int d = 0; d < 64; d++) {
            float4 wv = __ldg(wbase + (d << 5));
            float w0 = wv.x, w1 = wv.y, w2 = wv.z, w3 = wv.w;
            const float* hr = s_h2p + d * 68 + 4 * g;   // 16B aligned
            float4 lA = *(const float4*)(hr);
            float2 lB = *(const float2*)(hr + 4);
            float l0 = lA.x, l1 = lA.y, l2 = lA.z, l3 = lA.w, l4 = lB.x, l5 = lB.y;
            acc[0] += w1 * l1 + w3 * l0;
            acc[2] += w1 * l2 + w3 * l1;
            acc[4] += w1 * l3 + w3 * l2;
            acc[6] += w1 * l4 + w3 * l3;
            acc[1] += w0 * l2 + w2 * l1;
            acc[3] += w0 * l3 + w2 * l2;
            acc[5] += w0 * l4 + w2 * l3;
            acc[7] += w0 * l5 + w2 * l4;
        }
#pragma unroll
        for (int j = 0; j < 8; j++)
            s_dec[e * 132 + lb + j] = acc[j];
    }
    __syncthreads();

    // ---- projection: logits[l][v] = sum_e dec[e][l]*out_w[v][e] + out_b[v]
    //      4 v x 8 l per thread (32 acc regs, fits 64-reg budget) ----
    {
        int v0 = tid & 31;
        int grp = tid >> 5;        // 0..15
        int lb = grp * 8;
        float acc0[8], acc1[8], acc2[8], acc3[8];
#pragma unroll
        for (int j = 0; j < 8; j++) { acc0[j]=0.f; acc1[j]=0.f; acc2[j]=0.f; acc3[j]=0.f; }
#pragma unroll 4
        for (int e = 0; e < 32; e++) {
            float w0 = __ldg(g_owt + e * 128 + v0);
            float w1 = __ldg(g_owt + e * 128 + v0 + 32);
            float w2 = __ldg(g_owt + e * 128 + v0 + 64);
            float w3 = __ldg(g_owt + e * 128 + v0 + 96);
            const float4* dr4 = (const float4*)(s_dec + e * 132 + lb);
            float dl[8];
            *(float4*)(dl + 0) = dr4[0];
            *(float4*)(dl + 4) = dr4[1];
#pragma unroll
            for (int j = 0; j < 8; j++) {
                float dv = dl[j];
                acc0[j] += w0 * dv;
                acc1[j] += w1 * dv;
                acc2[j] += w2 * dv;
                acc3[j] += w3 * dv;
            }
        }
        float* lg = out + (long long)b * (128 * 128);
        float ob0 = __ldg(obg + v0);
        float ob1 = __ldg(obg + v0 + 32);
        float ob2 = __ldg(obg + v0 + 64);
        float ob3 = __ldg(obg + v0 + 96);
#pragma unroll
        for (int j = 0; j < 8; j++) {
            float* row = lg + (lb + j) * 128 + v0;
            row[0]  = acc0[j] + ob0;
            row[32] = acc1[j] + ob1;
            row[64] = acc2[j] + ob2;
            row[96] = acc3[j] + ob3;
        }
    }
}

// ---------------------------------------------------------------------------
__global__ void loss_kernel(float* __restrict__ out)
{
    __shared__ float red[256];
    int tid = threadIdx.x;
    float s = 0.f;
    for (int u = tid; u < B_; u += 256) s += g_loss[u];
    red[tid] = s;
    __syncthreads();
    for (int st = 128; st > 0; st >>= 1) {
        if (tid < st) red[tid] += red[tid + st];
        __syncthreads();
    }
    if (tid == 0)
        out[OFF_LOSS] = 1.25f * red[0] / (float)(B_ * 30 * 64);
}

// ---------------------------------------------------------------------------
extern "C" void kernel_launch(void* const* d_in, const int* in_sizes, int n_in,
                              void* d_out, int out_size)
{
    (void)in_sizes; (void)n_in; (void)out_size;
    const int*   tidx = (const int*)d_in[0];
    const float* emb  = (const float*)d_in[1];
    const float* ew1  = (const float*)d_in[2];
    const float* eb1  = (const float*)d_in[3];
    const float* ew2  = (const float*)d_in[4];
    const float* eb2  = (const float*)d_in[5];
    const float* ew3  = (const float*)d_in[6];
    const float* eb3  = (const float*)d_in[7];
    const float* cb   = (const float*)d_in[8];
    const float* dw1  = (const float*)d_in[9];
    const float* db1  = (const float*)d_in[10];
    const float* dw2  = (const float*)d_in[11];
    const float* db2  = (const float*)d_in[12];
    const float* dw3  = (const float*)d_in[13];
    const float* db3  = (const float*)d_in[14];
    const float* ow   = (const float*)d_in[15];
    const float* ob   = (const float*)d_in[16];
    float* out = (float*)d_out;

    cudaFuncSetAttribute(dec_kernel, cudaFuncAttributeMaxDynamicSharedMemorySize,
                         DEC_SMEM_BYTES);

    pre1_kernel<<<48, 512>>>(ew1, emb);
    pre2_kernel<<<4, 512>>>(dw1, cb);
    pre3_kernel<<<72, 512>>>(ew2, ew3, ow);
    enc_kernel<<<B_, 512>>>(tidx, eb1, eb2, eb3, cb);
    dec_kernel<<<B_, 512, DEC_SMEM_BYTES>>>(cb, db1, dw2, db2, dw3, db3, ob, out);
    loss_kernel<<<1, 256>>>(out);
}